// round 14
// baseline (speedup 1.0000x reference)
#include <cuda_runtime.h>
#include <cuda_bf16.h>
#include <math.h>
#include <stdint.h>

// ---------------- problem constants ----------------
#define D_MODEL 1024
#define NHEAD   16
#define HEAD_DIM 64
#define FF      4096
#define ALPHA   1.4142135f
#define EPS     1e-5f
#define BATCH   2
#define SEQ     2048
#define MTOT    (BATCH*SEQ)        // 4096 rows

// ---------------- scratch (device globals; no allocation allowed) ------------
__device__ float g_qkv[(size_t)MTOT * 3 * D_MODEL];
__device__ float g_a  [(size_t)MTOT * D_MODEL];
__device__ float g_x2 [(size_t)MTOT * D_MODEL];
__device__ float g_y2 [(size_t)MTOT * D_MODEL];
__device__ float g_rope[(size_t)SEQ * 64];                // cos[32] | sin[32] per t

// bf16 hi/lo split operands
__device__ __nv_bfloat16 g_xh [(size_t)MTOT * D_MODEL];
__device__ __nv_bfloat16 g_xl [(size_t)MTOT * D_MODEL];
__device__ __nv_bfloat16 g_oh [(size_t)MTOT * D_MODEL];
__device__ __nv_bfloat16 g_ol [(size_t)MTOT * D_MODEL];
__device__ __nv_bfloat16 g_x2h[(size_t)MTOT * D_MODEL];
__device__ __nv_bfloat16 g_x2l[(size_t)MTOT * D_MODEL];
__device__ __nv_bfloat16 g_hbh[(size_t)MTOT * FF];
__device__ __nv_bfloat16 g_hbl[(size_t)MTOT * FF];
__device__ __nv_bfloat16 g_wqh[(size_t)3*D_MODEL * D_MODEL];
__device__ __nv_bfloat16 g_wql[(size_t)3*D_MODEL * D_MODEL];
__device__ __nv_bfloat16 g_woh[(size_t)D_MODEL * D_MODEL];
__device__ __nv_bfloat16 g_w1h[(size_t)2*FF * D_MODEL];   // permuted y/gate interleave
__device__ __nv_bfloat16 g_w2h[(size_t)D_MODEL * FF];

// ---------------- PTX helpers -------------------------------------------------
__device__ __forceinline__ uint32_t smem_u32(const void* p) {
    uint32_t a;
    asm("{ .reg .u64 t; cvta.to.shared.u64 t, %1; cvt.u32.u64 %0, t; }" : "=r"(a) : "l"(p));
    return a;
}

#define CP_ASYNC16(dst, src) \
    asm volatile("cp.async.cg.shared.global [%0], [%1], 16;" :: "r"(dst), "l"(src) : "memory")
#define CP_COMMIT() asm volatile("cp.async.commit_group;" ::: "memory")

#define LDSM_X4(r0, r1, r2, r3, addr) \
    asm volatile("ldmatrix.sync.aligned.m8n8.x4.shared.b16 {%0,%1,%2,%3}, [%4];" \
        : "=r"(r0), "=r"(r1), "=r"(r2), "=r"(r3) : "r"(addr))

#define MMA_BF16(d, a, b0v, b1v) \
    asm volatile("mma.sync.aligned.m16n8k16.row.col.f32.bf16.bf16.f32 " \
        "{%0,%1,%2,%3}, {%4,%5,%6,%7}, {%8,%9}, {%0,%1,%2,%3};" \
        : "+f"((d)[0]), "+f"((d)[1]), "+f"((d)[2]), "+f"((d)[3]) \
        : "r"((a)[0]), "r"((a)[1]), "r"((a)[2]), "r"((a)[3]), "r"(b0v), "r"(b1v))

__device__ __forceinline__ void split2(float x, __nv_bfloat16& h, __nv_bfloat16& l) {
    h = __float2bfloat16_rn(x);
    l = __float2bfloat16_rn(x - __bfloat162float(h));
}

// MUFU-free exp: rel err ~2e-7, clamped
__device__ __forceinline__ float fexp(float x) {
    float t = x * 1.4426950408889634f;
    t = fminf(fmaxf(t, -126.f), 126.f);
    float fi = rintf(t);
    float f = t - fi;
    float p = 1.5403530393e-4f;
    p = p * f + 1.3333558146e-3f;
    p = p * f + 9.6181291076e-3f;
    p = p * f + 5.5504108664e-2f;
    p = p * f + 2.4022650696e-1f;
    p = p * f + 6.9314718056e-1f;
    p = p * f + 1.0f;
    int ei = (int)fi;
    return __int_as_float((uint32_t)(ei + 127) << 23) * p;
}

// MUFU-free reciprocal (Newton, 3 iters)
__device__ __forceinline__ float frcp(float d) {
    float r = __int_as_float(0x7EF311C3u - __float_as_int(d));
    r = r * (2.f - d * r);
    r = r * (2.f - d * r);
    r = r * (2.f - d * r);
    return r;
}

#define GETC(v, i) ((i) == 0 ? (v).x : (i) == 1 ? (v).y : (i) == 2 ? (v).z : (v).w)

// ---------------- HMMA GEMM, bf16 hi/lo, 128x128, 2 CTAs/SM -------------------
// NTERMS=3: C = Ah*Bh + Al*Bh + Ah*Bl  (3 stages, 32KB each)
// NTERMS=2: C = Ah*Bh + Al*Bh          (4 stages, 24KB each)
// Interleaved fragment loads: only afh+bfh before term0; afl (and bfl) LDSM
// issued between MMA groups so they overlap tensor execution.
#define GBM 128
#define GBN 128
#define GK  32
#define TAH (GBM*64)
#define TBH (GBN*64)

template<int MODE, int NTERMS>
__global__ void __launch_bounds__(256, 2)
gemm_mma(const __nv_bfloat16* __restrict__ Ah, const __nv_bfloat16* __restrict__ Al,
         const __nv_bfloat16* __restrict__ Bh, const __nv_bfloat16* __restrict__ Bl,
         float* __restrict__ C,
         __nv_bfloat16* __restrict__ Ho, __nv_bfloat16* __restrict__ Lo,
         int M, int N, int K)
{
    constexpr int STAGE_B = (NTERMS == 3 ? 4 : 3) * TAH;   // Ah,Al,Bh[,Bl]
    constexpr int NSTG    = (NTERMS == 3 ? 3 : 4);
    constexpr int PREF    = NSTG - 1;
    extern __shared__ __align__(128) char smem[];

    const int tid  = threadIdx.x;
    const int lane = tid & 31;
    const int wid  = tid >> 5;
    const int wm   = wid >> 2;
    const int wn   = wid & 3;
    const int bm   = blockIdx.y * GBM;
    const int bn   = blockIdx.x * GBN;

    const int NK = K / GK;
    const uint32_t sbase = smem_u32(smem);

    const int lrow = tid >> 2;
    const int lcc  = tid & 3;

    auto load_stage = [&](int s, int kc) {
        const uint32_t st = sbase + s * STAGE_B;
#pragma unroll
        for (int half = 0; half < 2; half++) {
            const int row = lrow + half * 64;
            const uint32_t swz = (uint32_t)(row * 64 + ((lcc ^ ((row >> 1) & 3)) << 4));
            const size_t ao = (size_t)(bm + row) * K + kc * GK + lcc * 8;
            const size_t bo = (size_t)(bn + row) * K + kc * GK + lcc * 8;
            CP_ASYNC16(st + swz,               Ah + ao);
            CP_ASYNC16(st + TAH + swz,         Al + ao);
            CP_ASYNC16(st + 2*TAH + swz,       Bh + bo);
            if (NTERMS == 3)
                CP_ASYNC16(st + 3*TAH + swz,   Bl + bo);
        }
    };

    float acc[4][4][4];
#pragma unroll
    for (int mi = 0; mi < 4; mi++)
#pragma unroll
        for (int ni = 0; ni < 4; ni++)
#pragma unroll
            for (int r = 0; r < 4; r++) acc[mi][ni][r] = 0.f;

#pragma unroll
    for (int s = 0; s < PREF; s++) { load_stage(s, s); CP_COMMIT(); }

    const int m_idx = lane >> 3;
    int scur = 0, sload = PREF;

    for (int c = 0; c < NK; c++) {
        if (NSTG == 4)
            asm volatile("cp.async.wait_group 2;" ::: "memory");
        else
            asm volatile("cp.async.wait_group 1;" ::: "memory");
        __syncthreads();
        if (c + PREF < NK) load_stage(sload, c + PREF);
        CP_COMMIT();
        if (++sload == NSTG) sload = 0;

        const uint32_t st = sbase + scur * STAGE_B;
        if (++scur == NSTG) scur = 0;

#pragma unroll
        for (int ks = 0; ks < 2; ks++) {
            uint32_t afh[4][4], afl[4][4], bfh[2][4], bfl[2][4];
            // --- phase 1: only the fragments term0 needs ---
#pragma unroll
            for (int mi = 0; mi < 4; mi++) {
                const int row = wm * 64 + mi * 16 + (lane & 7) + ((m_idx & 1) << 3);
                const int cch = 2 * ks + (m_idx >> 1);
                const uint32_t off = (uint32_t)(row * 64 + ((cch ^ ((row >> 1) & 3)) << 4));
                LDSM_X4(afh[mi][0], afh[mi][1], afh[mi][2], afh[mi][3], st + off);
            }
#pragma unroll
            for (int pi = 0; pi < 2; pi++) {
                const int nrow = wn * 32 + pi * 16 + (lane & 7) + ((m_idx >> 1) << 3);
                const int cch = 2 * ks + (m_idx & 1);
                const uint32_t off = (uint32_t)(nrow * 64 + ((cch ^ ((nrow >> 1) & 3)) << 4));
                LDSM_X4(bfh[pi][0], bfh[pi][1], bfh[pi][2], bfh[pi][3], st + 2*TAH + off);
            }
            // --- term 0: Ah x Bh ---
#pragma unroll
            for (int mi = 0; mi < 4; mi++)
#pragma unroll
                for (int ni = 0; ni < 4; ni++)
                    MMA_BF16(acc[mi][ni], afh[mi],
                             bfh[ni >> 1][(ni & 1) * 2], bfh[ni >> 1][(ni & 1) * 2 + 1]);
            // --- phase 2: Al fragments (overlap with term0 drain) ---
#pragma unroll
            for (int mi = 0; mi < 4; mi++) {
                const int row = wm * 64 + mi * 16 + (lane & 7) + ((m_idx & 1) << 3);
                const int cch = 2 * ks + (m_idx >> 1);
                const uint32_t off = (uint32_t)(row * 64 + ((cch ^ ((row >> 1) & 3)) << 4));
                LDSM_X4(afl[mi][0], afl[mi][1], afl[mi][2], afl[mi][3], st + TAH + off);
            }
            // --- term 1: Al x Bh ---
#pragma unroll
            for (int mi = 0; mi < 4; mi++)
#pragma unroll
                for (int ni = 0; ni < 4; ni++)
                    MMA_BF16(acc[mi][ni], afl[mi],
                             bfh[ni >> 1][(ni & 1) * 2], bfh[ni >> 1][(ni & 1) * 2 + 1]);
            if (NTERMS == 3) {
                // --- phase 3: Bl fragments ---
#pragma unroll
                for (int pi = 0; pi < 2; pi++) {
                    const int nrow = wn * 32 + pi * 16 + (lane & 7) + ((m_idx >> 1) << 3);
                    const int cch = 2 * ks + (m_idx & 1);
                    const uint32_t off = (uint32_t)(nrow * 64 + ((cch ^ ((nrow >> 1) & 3)) << 4));
                    LDSM_X4(bfl[pi][0], bfl[pi][1], bfl[pi][2], bfl[pi][3], st + 2*TAH + TBH + off);
                }
                // --- term 2: Ah x Bl ---
#pragma unroll
                for (int mi = 0; mi < 4; mi++)
#pragma unroll
                    for (int ni = 0; ni < 4; ni++)
                        MMA_BF16(acc[mi][ni], afh[mi],
                                 bfl[ni >> 1][(ni & 1) * 2], bfl[ni >> 1][(ni & 1) * 2 + 1]);
            }
        }
    }

    // epilogue
#pragma unroll
    for (int mi = 0; mi < 4; mi++) {
        const int row0 = bm + wm * 64 + mi * 16 + (lane >> 2);
#pragma unroll
        for (int ni = 0; ni < 4; ni++) {
            const int col = bn + wn * 32 + ni * 8 + (lane & 3) * 2;
            if (MODE == 0) {
                *(float2*)(C + (size_t)row0 * N + col)       = make_float2(acc[mi][ni][0], acc[mi][ni][1]);
                *(float2*)(C + (size_t)(row0 + 8) * N + col) = make_float2(acc[mi][ni][2], acc[mi][ni][3]);
            } else {
                const int Nout = N >> 1;
                const int j = col >> 1;
                float y0 = acc[mi][ni][0], gt0 = acc[mi][ni][1];
                float y1 = acc[mi][ni][2], gt1 = acc[mi][ni][3];
                float h0 = y0 * gt0 * frcp(1.f + fexp(-gt0));
                float h1 = y1 * gt1 * frcp(1.f + fexp(-gt1));
                __nv_bfloat16 hh, ll;
                split2(h0, hh, ll);
                Ho[(size_t)row0 * Nout + j] = hh;
                Lo[(size_t)row0 * Nout + j] = ll;
                split2(h1, hh, ll);
                Ho[(size_t)(row0 + 8) * Nout + j] = hh;
                Lo[(size_t)(row0 + 8) * Nout + j] = ll;
            }
        }
    }
}

// ---------------- weight splits -----------------------------------------------
#define NW_WQ  (3*D_MODEL*D_MODEL/4)
#define NW_WO  (D_MODEL*D_MODEL/4)
#define NW_A   (NW_WQ + NW_WO)
#define NW_W1  (2*FF*D_MODEL/4)
#define NW_W2  (D_MODEL*FF/4)
#define NW_B   (NW_W1 + NW_W2)

__global__ void __launch_bounds__(256)
split_wA(const float* __restrict__ Wqkv, const float* __restrict__ Wout,
         __nv_bfloat16* __restrict__ wqh, __nv_bfloat16* __restrict__ wql,
         __nv_bfloat16* __restrict__ woh)
{
    int i = blockIdx.x * blockDim.x + threadIdx.x;
    if (i >= NW_A) return;
    if (i < NW_WQ) {
        float4 v = ((const float4*)Wqkv)[i];
        __nv_bfloat16 h[4], l[4];
        split2(v.x, h[0], l[0]); split2(v.y, h[1], l[1]);
        split2(v.z, h[2], l[2]); split2(v.w, h[3], l[3]);
        ((uint2*)wqh)[i] = *(uint2*)h;
        ((uint2*)wql)[i] = *(uint2*)l;
        return;
    }
    size_t o = i - NW_WQ;
    float4 v = ((const float4*)Wout)[o];
    __nv_bfloat16 h[4];
    h[0] = __float2bfloat16_rn(v.x); h[1] = __float2bfloat16_rn(v.y);
    h[2] = __float2bfloat16_rn(v.z); h[3] = __float2bfloat16_rn(v.w);
    ((uint2*)woh)[o] = *(uint2*)h;
}

__global__ void __launch_bounds__(256)
split_wB(const float* __restrict__ W1, const float* __restrict__ W2,
         __nv_bfloat16* __restrict__ w1h, __nv_bfloat16* __restrict__ w2h)
{
    int i = blockIdx.x * blockDim.x + threadIdx.x;
    if (i >= NW_B) return;
    if (i < NW_W1) {
        int flat = i * 4;
        int row = flat >> 10;
        int col = flat & (D_MODEL - 1);
        int prow = (row < FF) ? (2 * row) : (2 * (row - FF) + 1);
        float4 v = ((const float4*)W1)[i];
        __nv_bfloat16 h[4];
        h[0] = __float2bfloat16_rn(v.x); h[1] = __float2bfloat16_rn(v.y);
        h[2] = __float2bfloat16_rn(v.z); h[3] = __float2bfloat16_rn(v.w);
        ((uint2*)w1h)[((size_t)prow * D_MODEL + col) >> 2] = *(uint2*)h;
        return;
    }
    size_t o = i - NW_W1;
    float4 v = ((const float4*)W2)[o];
    __nv_bfloat16 h[4];
    h[0] = __float2bfloat16_rn(v.x); h[1] = __float2bfloat16_rn(v.y);
    h[2] = __float2bfloat16_rn(v.z); h[3] = __float2bfloat16_rn(v.w);
    ((uint2*)w2h)[o] = *(uint2*)h;
}

// ---------------- x split + rope table ----------------------------------------
#define NX_X   (MTOT*D_MODEL/4)
#define NX_ROPE (SEQ*32)
#define NX_TOTAL (NX_X + NX_ROPE)

__global__ void __launch_bounds__(256)
split_x_rope(const float* __restrict__ x,
             __nv_bfloat16* __restrict__ xh, __nv_bfloat16* __restrict__ xl,
             float* __restrict__ rope)
{
    int i = blockIdx.x * blockDim.x + threadIdx.x;
    if (i >= NX_TOTAL) return;
    if (i >= NX_X) {
        int j = i - NX_X;
        int t = j >> 5, dd = j & 31;
        float inv = powf(10000.0f, -(float)dd / 32.0f);
        float s, c;
        sincosf((float)t * inv, &s, &c);
        rope[t * 64 + dd]      = c;
        rope[t * 64 + 32 + dd] = s;
        return;
    }
    float4 v = ((const float4*)x)[i];
    __nv_bfloat16 h[4], l[4];
    split2(v.x, h[0], l[0]); split2(v.y, h[1], l[1]);
    split2(v.z, h[2], l[2]); split2(v.w, h[3], l[3]);
    ((uint2*)xh)[i] = *(uint2*)h;
    ((uint2*)xl)[i] = *(uint2*)l;
}

// ---------------- banded attention v5 (R11) -----------------------------------
#define QTILE 64
#define NKMAX 320
#define PADK  324
#define PADV  68
#define NCH2  5
#define ATTN_SMEM ((64*PADK + NKMAX*PADV + 64*PADV) * sizeof(float))

__global__ void __launch_bounds__(512)
attn_kernel(const float* __restrict__ qkv, const float* __restrict__ rope,
            __nv_bfloat16* __restrict__ OH, __nv_bfloat16* __restrict__ OL)
{
    extern __shared__ float sm[];
    float* KT = sm;
    float* Vs = sm + 64 * PADK;
    float* Qs = Vs + NKMAX * PADV;

    const int bh = blockIdx.y;
    const int b = bh >> 4, h = bh & 15;
    const int q0 = blockIdx.x * QTILE;
    const int klo = max(0, q0 - 127);
    const int khi = min(SEQ - 1, q0 + QTILE - 1 + 128);
    const int nk = khi - klo + 1;

    const int tid = threadIdx.x;

    for (int i = tid; i < nk * 32; i += 512) {
        int r = i >> 5, dd = i & 31;
        int t = klo + r;
        const float* base = qkv + (size_t)(b * SEQ + t) * (3 * D_MODEL) + h * HEAD_DIM;
        float c0 = rope[t * 64 + dd], s0 = rope[t * 64 + 32 + dd];
        float k1 = base[D_MODEL + dd], k2 = base[D_MODEL + 32 + dd];
        KT[dd * PADK + r]        = k1 * c0 - k2 * s0;
        KT[(dd + 32) * PADK + r] = k2 * c0 + k1 * s0;
        Vs[r * PADV + dd]        = base[2 * D_MODEL + dd];
        Vs[r * PADV + 32 + dd]   = base[2 * D_MODEL + 32 + dd];
    }
    for (int i = tid; i < 64 * 8; i += 512) {
        int dd = i >> 3, r = nk + (i & 7);
        if (r < NKMAX) KT[dd * PADK + r] = 0.f;
    }
    for (int i = tid; i < QTILE * 32; i += 512) {
        int r = i >> 5, dd = i & 31;
        int t = q0 + r;
        const float* base = qkv + (size_t)(b * SEQ + t) * (3 * D_MODEL) + h * HEAD_DIM;
        float c0 = rope[t * 64 + dd], s0 = rope[t * 64 + 32 + dd];
        float q1 = base[dd], q2 = base[32 + dd];
        Qs[r * PADV + dd]      = q1 * c0 - q2 * s0;
        Qs[r * PADV + 32 + dd] = q2 * c0 + q1 * s0;
    }
    __syncthreads();

    const int w = tid >> 5, lane = tid & 31;
    const int qloc = w * 4;
    const int qg0 = q0 + qloc;

    float2 acc[4][NCH2];
#pragma unroll
    for (int j = 0; j < 4; j++)
#pragma unroll
        for (int c = 0; c < NCH2; c++) acc[j][c] = make_float2(0.f, 0.f);

    for (int db = 0; db < HEAD_DIM; db += 4) {
        float4 q4[4];
#pragma unroll
        for (int j = 0; j < 4; j++)
            q4[j] = *(const float4*)&Qs[(qloc + j) * PADV + db];
#pragma unroll
        for (int dd = 0; dd < 4; dd++) {
            float qa = GETC(q4[0], dd);
            float qb = GETC(q4[1], dd);
            float qc = GETC(q4[2], dd);
            float qd = GETC(q4[3], dd);
            const float2* kt = (const float2*)(KT + (db + dd) * PADK) + lane;
#pragma unroll
            for (int c = 0; c < NCH2; c++) {
                float2 kv = kt[c * 32];
                acc[0][c].x += qa * kv.x; acc[0][c].y += qa * kv.y;
                acc[1][c].x += qb * kv.x; acc[1][c].y += qb * kv.y;
                acc[2][c].x += qc * kv.x; acc[2][c].y += qc * kv.y;
                acc[3][c].x += qd * kv.x; acc[3][c].y += qd * kv.y;
            }
        }
    }

    float inv[4];
#pragma unroll
    for (int j = 0; j < 4; j++) {
        const int qg = qg0 + j;
        const int lo = max(0, qg - 127) - klo;
        const int hi = min(SEQ - 1, qg + 128) - klo;
        float m = -1e30f;
#pragma unroll
        for (int c = 0; c < NCH2; c++) {
            int kg = c * 64 + 2 * lane;
            float sx = (kg     >= lo && kg     <= hi) ? acc[j][c].x * 0.125f : -1e30f;
            float sy = (kg + 1 >= lo && kg + 1 <= hi) ? acc[j][c].y * 0.125f : -1e30f;
            acc[j][c].x = sx; acc[j][c].y = sy;
            m = fmaxf(m, fmaxf(sx, sy));
        }
#pragma unroll
        for (int o = 16; o; o >>= 1) m = fmaxf(m, __shfl_xor_sync(0xffffffffu, m, o));
        float sum = 0.f;
#pragma unroll
        for (int c = 0; c < NCH2; c++) {
            float ex = fexp(acc[j][c].x - m);
            float ey = fexp(acc[j][c].y - m);
            acc[j][c].x = ex; acc[j][c].y = ey;
            sum += ex + ey;
        }
#pragma unroll
        for (int o = 16; o; o >>= 1) sum += __shfl_xor_sync(0xffffffffu, sum, o);
        inv[j] = frcp(sum);
    }

    __syncthreads();
    float* P = KT;
#pragma unroll
    for (int j = 0; j < 4; j++) {
        float2* prow = (float2*)(P + (qloc + j) * PADK) + lane;
#pragma unroll
        for (int c = 0; c < NCH2; c++)
            prow[c * 32] = make_float2(acc[j][c].x * inv[j], acc[j][c].y * inv[j]);
    }
    __syncthreads();

    const int kstart = (max(0, qg0 - 127) - klo) & ~3;
    const int kend   = min(SEQ - 1, qg0 + 3 + 128) - klo;

    float ox0 = 0.f, oy0 = 0.f, ox1 = 0.f, oy1 = 0.f;
    float ox2 = 0.f, oy2 = 0.f, ox3 = 0.f, oy3 = 0.f;
    const float* p0 = P + (qloc + 0) * PADK;
    const float* p1 = P + (qloc + 1) * PADK;
    const float* p2 = P + (qloc + 2) * PADK;
    const float* p3 = P + (qloc + 3) * PADK;

    int k = kstart;
    for (; k + 3 <= kend; k += 4) {
        float2 v0 = *(const float2*)&Vs[(k + 0) * PADV + 2 * lane];
        float2 v1 = *(const float2*)&Vs[(k + 1) * PADV + 2 * lane];
        float2 v2 = *(const float2*)&Vs[(k + 2) * PADV + 2 * lane];
        float2 v3 = *(const float2*)&Vs[(k + 3) * PADV + 2 * lane];
        float4 a0 = *(const float4*)&p0[k];
        float4 a1 = *(const float4*)&p1[k];
        float4 a2 = *(const float4*)&p2[k];
        float4 a3 = *(const float4*)&p3[k];
        ox0 += a0.x * v0.x + a0.y * v1.x + a0.z * v2.x + a0.w * v3.x;
        oy0 += a0.x * v0.y + a0.y * v1.y + a0.z * v2.y + a0.w * v3.y;
        ox1 += a1.x * v0.x + a1.y * v1.x + a1.z * v2.x + a1.w * v3.x;
        oy1 += a1.x * v0.y + a1.y * v1.y + a1.z * v2.y + a1.w * v3.y;
        ox2 += a2.x * v0.x + a2.y * v1.x + a2.z * v2.x + a2.w * v3.x;
        oy2 += a2.x * v0.y + a2.y * v1.y + a2.z * v2.y + a2.w * v3.y;
        ox3 += a3.x * v0.x + a3.y * v1.x + a3.z * v2.x + a3.w * v3.x;
        oy3 += a3.x * v0.y + a3.y * v1.y + a3.z * v2.y + a3.w * v3.y;
    }
    for (; k <= kend; k++) {
        float2 va = *(const float2*)&Vs[k * PADV + 2 * lane];
        float a0 = p0[k], a1 = p1[k], a2 = p2[k], a3 = p3[k];
        ox0 += a0 * va.x; oy0 += a0 * va.y;
        ox1 += a1 * va.x; oy1 += a1 * va.y;
        ox2 += a2 * va.x; oy2 += a2 * va.y;
        ox3 += a3 * va.x; oy3 += a3 * va.y;
    }

    float oxv[4] = {ox0, ox1, ox2, ox3};
    float oyv[4] = {oy0, oy1, oy2, oy3};
#pragma unroll
    for (int j = 0; j < 4; j++) {
        size_t ob = ((size_t)(b * SEQ + qg0 + j)) * D_MODEL + h * HEAD_DIM + 2 * lane;
        __nv_bfloat16 hx, lx, hy, ly;
        split2(oxv[j], hx, lx);
        split2(oyv[j], hy, ly);
        __nv_bfloat162 hp; hp.x = hx; hp.y = hy;
        __nv_bfloat162 lp; lp.x = lx; lp.y = ly;
        *(__nv_bfloat162*)(OH + ob) = hp;
        *(__nv_bfloat162*)(OL + ob) = lp;
    }
}

// ---------------- residual + (opt bias) + RMSNorm (+opt bf16 split out) ------
__global__ void __launch_bounds__(256)
resid_rmsnorm(const float* __restrict__ A, const float* __restrict__ bias,
              const float* __restrict__ R, const float* __restrict__ g,
              float* __restrict__ out,
              __nv_bfloat16* __restrict__ outH, __nv_bfloat16* __restrict__ outL)
{
    const int row = blockIdx.x;
    const float* a = A + (size_t)row * D_MODEL;
    const float* r = R + (size_t)row * D_MODEL;

    float v[4];
    float ss = 0.f;
#pragma unroll
    for (int i = 0; i < 4; i++) {
        int c = threadIdx.x + i * 256;
        float x = a[c] + ALPHA * r[c];
        if (bias) x += bias[c];
        v[i] = x;
        ss += x * x;
    }
#pragma unroll
    for (int o = 16; o; o >>= 1) ss += __shfl_xor_sync(0xffffffffu, ss, o);

    __shared__ float ws[8];
    if ((threadIdx.x & 31) == 0) ws[threadIdx.x >> 5] = ss;
    __syncthreads();
    if (threadIdx.x < 32) {
        float t = (threadIdx.x < 8) ? ws[threadIdx.x] : 0.f;
#pragma unroll
        for (int o = 4; o; o >>= 1) t += __shfl_xor_sync(0xffffffffu, t, o);
        if (threadIdx.x == 0) ws[0] = t;
    }
    __syncthreads();
    const float rms = rsqrtf(ws[0] * (1.0f / D_MODEL) + EPS);

    float* orow = out + (size_t)row * D_MODEL;
#pragma unroll
    for (int i = 0; i < 4; i++) {
        int c = threadIdx.x + i * 256;
        float y = v[i] * rms * g[c];
        orow[c] = y;
        if (outH) {
            __nv_bfloat16 h, l;
            split2(y, h, l);
            outH[(size_t)row * D_MODEL + c] = h;
            outL[(size_t)row * D_MODEL + c] = l;
        }
    }
}

// ---------------- host orchestration -----------------------------------------
template<int MODE, int NTERMS>
static void launch_gemm(const __nv_bfloat16* Ah, const __nv_bfloat16* Al,
                        const __nv_bfloat16* Bh, const __nv_bfloat16* Bl,
                        float* C, __nv_bfloat16* Ho, __nv_bfloat16* Lo,
                        int M, int N, int K)
{
    const int stage = (NTERMS == 3 ? 4 : 3) * TAH;
    const int nstg  = (NTERMS == 3 ? 3 : 4);
    size_t smem = (size_t)nstg * stage;
    cudaFuncSetAttribute(gemm_mma<MODE, NTERMS>, cudaFuncAttributeMaxDynamicSharedMemorySize, (int)smem);
    dim3 grid(N / GBN, M / GBM);
    gemm_mma<MODE, NTERMS><<<grid, 256, smem>>>(Ah, Al, Bh, Bl, C, Ho, Lo, M, N, K);
}

extern "C" void kernel_launch(void* const* d_in, const int* in_sizes, int n_in,
                              void* d_out, int out_size)
{
    const float* x    = (const float*)d_in[0];
    const float* Wqkv = (const float*)d_in[1];
    const float* Wout = (const float*)d_in[2];
    const float* bout = (const float*)d_in[3];
    const float* W1   = (const float*)d_in[4];
    const float* W2   = (const float*)d_in[5];
    const float* g1   = (const float*)d_in[6];
    const float* g2   = (const float*)d_in[7];
    float* out = (float*)d_out;

    float *qkv, *Ap, *x2, *y2, *rope;
    cudaGetSymbolAddress((void**)&qkv,  g_qkv);
    cudaGetSymbolAddress((void**)&Ap,   g_a);
    cudaGetSymbolAddress((void**)&x2,   g_x2);
    cudaGetSymbolAddress((void**)&y2,   g_y2);
    cudaGetSymbolAddress((void**)&rope, g_rope);

    __nv_bfloat16 *xh,*xl,*oh,*ol,*x2h,*x2l,*hbh,*hbl,*wqh,*wql,*woh,*w1h,*w2h;
    cudaGetSymbolAddress((void**)&xh,  g_xh);  cudaGetSymbolAddress((void**)&xl,  g_xl);
    cudaGetSymbolAddress((void**)&oh,  g_oh);  cudaGetSymbolAddress((void**)&ol,  g_ol);
    cudaGetSymbolAddress((void**)&x2h, g_x2h); cudaGetSymbolAddress((void**)&x2l, g_x2l);
    cudaGetSymbolAddress((void**)&hbh, g_hbh); cudaGetSymbolAddress((void**)&hbl, g_hbl);
    cudaGetSymbolAddress((void**)&wqh, g_wqh); cudaGetSymbolAddress((void**)&wql, g_wql);
    cudaGetSymbolAddress((void**)&woh, g_woh);
    cudaGetSymbolAddress((void**)&w1h, g_w1h);
    cudaGetSymbolAddress((void**)&w2h, g_w2h);

    // 0) weight split A (Wqkv hi+lo, Wout hi)                          [launch 0]
    split_wA<<<(NW_A + 255) / 256, 256>>>(Wqkv, Wout, wqh, wql, woh);

    // 1) weight split B (W1 perm hi, W2 hi)                            [launch 1]
    split_wB<<<(NW_B + 255) / 256, 256>>>(W1, W2, w1h, w2h);

    // 2) x split + rope table                                          [launch 2]
    split_x_rope<<<(NX_TOTAL + 255) / 256, 256>>>(x, xh, xl, rope);

    // 3) QKV = X @ Wqkv^T  (3-term)                       [launch 3 -> profiled]
    launch_gemm<0, 3>(xh, xl, wqh, wql, qkv, nullptr, nullptr, MTOT, 3 * D_MODEL, D_MODEL);

    // 4) banded attention (rope fused) -> oh/ol                        [launch 4]
    {
        cudaFuncSetAttribute(attn_kernel, cudaFuncAttributeMaxDynamicSharedMemorySize, (int)ATTN_SMEM);
        dim3 grid(SEQ / QTILE, BATCH * NHEAD);
        attn_kernel<<<grid, 512, ATTN_SMEM>>>(qkv, rope, oh, ol);
    }

    // 5) A = O @ Wout^T  (2-term, 4-stage)                             [launch 5]
    launch_gemm<0, 2>(oh, ol, woh, nullptr, Ap, nullptr, nullptr, MTOT, D_MODEL, D_MODEL);

    // 6) x2 = rmsnorm(A + bout + ALPHA*x, g1) (+ bf16 split)           [launch 6]
    resid_rmsnorm<<<MTOT, 256>>>(Ap, bout, x, g1, x2, x2h, x2l);

    // 7) fused: [y|gate] = x2 @ W1perm^T, swiglu (2-term, 4-stage)     [launch 7]
    launch_gemm<1, 2>(x2h, x2l, w1h, nullptr, nullptr, hbh, hbl, MTOT, 2 * FF, D_MODEL);

    // 8) Y2 = H @ W2^T  (K = FF, 2-term, 4-stage)                      [launch 8]
    launch_gemm<0, 2>(hbh, hbl, w2h, nullptr, y2, nullptr, nullptr, MTOT, D_MODEL, FF);

    // 9) out = rmsnorm(Y2 + ALPHA*x2, g2)                              [launch 9]
    resid_rmsnorm<<<MTOT, 256>>>(y2, nullptr, x2, g2, out, nullptr, nullptr);
}

// round 15
// speedup vs baseline: 1.0542x; 1.0542x over previous
#include <cuda_runtime.h>
#include <cuda_bf16.h>
#include <math.h>
#include <stdint.h>

// ---------------- problem constants ----------------
#define D_MODEL 1024
#define NHEAD   16
#define HEAD_DIM 64
#define FF      4096
#define ALPHA   1.4142135f
#define EPS     1e-5f
#define BATCH   2
#define SEQ     2048
#define MTOT    (BATCH*SEQ)        // 4096 rows

// ---------------- scratch (device globals; no allocation allowed) ------------
__device__ float g_qkv[(size_t)MTOT * 3 * D_MODEL];
__device__ float g_a  [(size_t)MTOT * D_MODEL];
__device__ float g_x2 [(size_t)MTOT * D_MODEL];
__device__ float g_y2 [(size_t)MTOT * D_MODEL];
__device__ float g_rope[(size_t)SEQ * 64];                // cos[32] | sin[32] per t

// bf16 hi/lo split operands
__device__ __nv_bfloat16 g_xh [(size_t)MTOT * D_MODEL];
__device__ __nv_bfloat16 g_xl [(size_t)MTOT * D_MODEL];
__device__ __nv_bfloat16 g_oh [(size_t)MTOT * D_MODEL];
__device__ __nv_bfloat16 g_ol [(size_t)MTOT * D_MODEL];
__device__ __nv_bfloat16 g_x2h[(size_t)MTOT * D_MODEL];
__device__ __nv_bfloat16 g_x2l[(size_t)MTOT * D_MODEL];
__device__ __nv_bfloat16 g_hbh[(size_t)MTOT * FF];
__device__ __nv_bfloat16 g_hbl[(size_t)MTOT * FF];
__device__ __nv_bfloat16 g_wqh[(size_t)3*D_MODEL * D_MODEL];
__device__ __nv_bfloat16 g_wql[(size_t)3*D_MODEL * D_MODEL];
__device__ __nv_bfloat16 g_woh[(size_t)D_MODEL * D_MODEL];
__device__ __nv_bfloat16 g_w1h[(size_t)2*FF * D_MODEL];   // permuted y/gate interleave
__device__ __nv_bfloat16 g_w2h[(size_t)D_MODEL * FF];

// ---------------- PTX helpers -------------------------------------------------
__device__ __forceinline__ uint32_t smem_u32(const void* p) {
    uint32_t a;
    asm("{ .reg .u64 t; cvta.to.shared.u64 t, %1; cvt.u32.u64 %0, t; }" : "=r"(a) : "l"(p));
    return a;
}

#define CP_ASYNC16(dst, src) \
    asm volatile("cp.async.cg.shared.global [%0], [%1], 16;" :: "r"(dst), "l"(src) : "memory")
#define CP_COMMIT() asm volatile("cp.async.commit_group;" ::: "memory")

#define LDSM_X4(r0, r1, r2, r3, addr) \
    asm volatile("ldmatrix.sync.aligned.m8n8.x4.shared.b16 {%0,%1,%2,%3}, [%4];" \
        : "=r"(r0), "=r"(r1), "=r"(r2), "=r"(r3) : "r"(addr))

#define MMA_BF16(d, a, b0v, b1v) \
    asm volatile("mma.sync.aligned.m16n8k16.row.col.f32.bf16.bf16.f32 " \
        "{%0,%1,%2,%3}, {%4,%5,%6,%7}, {%8,%9}, {%0,%1,%2,%3};" \
        : "+f"((d)[0]), "+f"((d)[1]), "+f"((d)[2]), "+f"((d)[3]) \
        : "r"((a)[0]), "r"((a)[1]), "r"((a)[2]), "r"((a)[3]), "r"(b0v), "r"(b1v))

__device__ __forceinline__ void split2(float x, __nv_bfloat16& h, __nv_bfloat16& l) {
    h = __float2bfloat16_rn(x);
    l = __float2bfloat16_rn(x - __bfloat162float(h));
}

// MUFU-free exp: rel err ~2e-7, clamped
__device__ __forceinline__ float fexp(float x) {
    float t = x * 1.4426950408889634f;
    t = fminf(fmaxf(t, -126.f), 126.f);
    float fi = rintf(t);
    float f = t - fi;
    float p = 1.5403530393e-4f;
    p = p * f + 1.3333558146e-3f;
    p = p * f + 9.6181291076e-3f;
    p = p * f + 5.5504108664e-2f;
    p = p * f + 2.4022650696e-1f;
    p = p * f + 6.9314718056e-1f;
    p = p * f + 1.0f;
    int ei = (int)fi;
    return __int_as_float((uint32_t)(ei + 127) << 23) * p;
}

// MUFU-free reciprocal (Newton, 3 iters)
__device__ __forceinline__ float frcp(float d) {
    float r = __int_as_float(0x7EF311C3u - __float_as_int(d));
    r = r * (2.f - d * r);
    r = r * (2.f - d * r);
    r = r * (2.f - d * r);
    return r;
}

#define GETC(v, i) ((i) == 0 ? (v).x : (i) == 1 ? (v).y : (i) == 2 ? (v).z : (v).w)

// ---------------- HMMA GEMM, bf16 hi/lo, 128x128, 2 CTAs/SM -------------------
// NTERMS=3: C = Ah*Bh + Al*Bh + Ah*Bl  (3 stages, 32KB each)
// NTERMS=2: C = Ah*Bh + Al*Bh          (4 stages, 24KB each)
// MODE 0: fp32 C.  MODE 1: (y,gate) col pairs -> swiglu -> bf16 h/l.
#define GBM 128
#define GBN 128
#define GK  32
#define TAH (GBM*64)
#define TBH (GBN*64)

template<int MODE, int NTERMS>
__global__ void __launch_bounds__(256, 2)
gemm_mma(const __nv_bfloat16* __restrict__ Ah, const __nv_bfloat16* __restrict__ Al,
         const __nv_bfloat16* __restrict__ Bh, const __nv_bfloat16* __restrict__ Bl,
         float* __restrict__ C,
         __nv_bfloat16* __restrict__ Ho, __nv_bfloat16* __restrict__ Lo,
         int M, int N, int K)
{
    constexpr int STAGE_B = (NTERMS == 3 ? 4 : 3) * TAH;   // Ah,Al,Bh[,Bl]
    constexpr int NSTG    = (NTERMS == 3 ? 3 : 4);
    constexpr int PREF    = NSTG - 1;                      // prefetch distance
    extern __shared__ __align__(128) char smem[];

    const int tid  = threadIdx.x;
    const int lane = tid & 31;
    const int wid  = tid >> 5;
    const int wm   = wid >> 2;
    const int wn   = wid & 3;
    const int bm   = blockIdx.y * GBM;
    const int bn   = blockIdx.x * GBN;

    const int NK = K / GK;
    const uint32_t sbase = smem_u32(smem);

    const int lrow = tid >> 2;
    const int lcc  = tid & 3;

    auto load_stage = [&](int s, int kc) {
        const uint32_t st = sbase + s * STAGE_B;
#pragma unroll
        for (int half = 0; half < 2; half++) {
            const int row = lrow + half * 64;
            const uint32_t swz = (uint32_t)(row * 64 + ((lcc ^ ((row >> 1) & 3)) << 4));
            const size_t ao = (size_t)(bm + row) * K + kc * GK + lcc * 8;
            const size_t bo = (size_t)(bn + row) * K + kc * GK + lcc * 8;
            CP_ASYNC16(st + swz,               Ah + ao);
            CP_ASYNC16(st + TAH + swz,         Al + ao);
            CP_ASYNC16(st + 2*TAH + swz,       Bh + bo);
            if (NTERMS == 3)
                CP_ASYNC16(st + 3*TAH + swz,   Bl + bo);
        }
    };

    float acc[4][4][4];
#pragma unroll
    for (int mi = 0; mi < 4; mi++)
#pragma unroll
        for (int ni = 0; ni < 4; ni++)
#pragma unroll
            for (int r = 0; r < 4; r++) acc[mi][ni][r] = 0.f;

    // prologue: fill NSTG-1 stages
#pragma unroll
    for (int s = 0; s < PREF; s++) { load_stage(s, s); CP_COMMIT(); }

    const int m_idx = lane >> 3;
    int scur = 0, sload = PREF;

    for (int c = 0; c < NK; c++) {
        if (NSTG == 4)
            asm volatile("cp.async.wait_group 2;" ::: "memory");
        else
            asm volatile("cp.async.wait_group 1;" ::: "memory");
        __syncthreads();
        if (c + PREF < NK) load_stage(sload, c + PREF);
        CP_COMMIT();
        if (++sload == NSTG) sload = 0;

        const uint32_t st = sbase + scur * STAGE_B;
        if (++scur == NSTG) scur = 0;

#pragma unroll
        for (int ks = 0; ks < 2; ks++) {
            uint32_t afh[4][4], afl[4][4], bfh[2][4], bfl[2][4];
#pragma unroll
            for (int mi = 0; mi < 4; mi++) {
                const int row = wm * 64 + mi * 16 + (lane & 7) + ((m_idx & 1) << 3);
                const int cch = 2 * ks + (m_idx >> 1);
                const uint32_t off = (uint32_t)(row * 64 + ((cch ^ ((row >> 1) & 3)) << 4));
                LDSM_X4(afh[mi][0], afh[mi][1], afh[mi][2], afh[mi][3], st + off);
                LDSM_X4(afl[mi][0], afl[mi][1], afl[mi][2], afl[mi][3], st + TAH + off);
            }
#pragma unroll
            for (int pi = 0; pi < 2; pi++) {
                const int nrow = wn * 32 + pi * 16 + (lane & 7) + ((m_idx >> 1) << 3);
                const int cch = 2 * ks + (m_idx & 1);
                const uint32_t off = (uint32_t)(nrow * 64 + ((cch ^ ((nrow >> 1) & 3)) << 4));
                LDSM_X4(bfh[pi][0], bfh[pi][1], bfh[pi][2], bfh[pi][3], st + 2*TAH + off);
                if (NTERMS == 3)
                    LDSM_X4(bfl[pi][0], bfl[pi][1], bfl[pi][2], bfl[pi][3], st + 2*TAH + TBH + off);
            }
#pragma unroll
            for (int mi = 0; mi < 4; mi++)
#pragma unroll
                for (int ni = 0; ni < 4; ni++)
                    MMA_BF16(acc[mi][ni], afh[mi],
                             bfh[ni >> 1][(ni & 1) * 2], bfh[ni >> 1][(ni & 1) * 2 + 1]);
#pragma unroll
            for (int mi = 0; mi < 4; mi++)
#pragma unroll
                for (int ni = 0; ni < 4; ni++)
                    MMA_BF16(acc[mi][ni], afl[mi],
                             bfh[ni >> 1][(ni & 1) * 2], bfh[ni >> 1][(ni & 1) * 2 + 1]);
            if (NTERMS == 3) {
#pragma unroll
                for (int mi = 0; mi < 4; mi++)
#pragma unroll
                    for (int ni = 0; ni < 4; ni++)
                        MMA_BF16(acc[mi][ni], afh[mi],
                                 bfl[ni >> 1][(ni & 1) * 2], bfl[ni >> 1][(ni & 1) * 2 + 1]);
            }
        }
    }

    // epilogue
#pragma unroll
    for (int mi = 0; mi < 4; mi++) {
        const int row0 = bm + wm * 64 + mi * 16 + (lane >> 2);
#pragma unroll
        for (int ni = 0; ni < 4; ni++) {
            const int col = bn + wn * 32 + ni * 8 + (lane & 3) * 2;
            if (MODE == 0) {
                *(float2*)(C + (size_t)row0 * N + col)       = make_float2(acc[mi][ni][0], acc[mi][ni][1]);
                *(float2*)(C + (size_t)(row0 + 8) * N + col) = make_float2(acc[mi][ni][2], acc[mi][ni][3]);
            } else {
                const int Nout = N >> 1;
                const int j = col >> 1;
                float y0 = acc[mi][ni][0], gt0 = acc[mi][ni][1];
                float y1 = acc[mi][ni][2], gt1 = acc[mi][ni][3];
                float h0 = y0 * gt0 * frcp(1.f + fexp(-gt0));
                float h1 = y1 * gt1 * frcp(1.f + fexp(-gt1));
                __nv_bfloat16 hh, ll;
                split2(h0, hh, ll);
                Ho[(size_t)row0 * Nout + j] = hh;
                Lo[(size_t)row0 * Nout + j] = ll;
                split2(h1, hh, ll);
                Ho[(size_t)(row0 + 8) * Nout + j] = hh;
                Lo[(size_t)(row0 + 8) * Nout + j] = ll;
            }
        }
    }
}

// ---------------- weight splits -----------------------------------------------
#define NW_WQ  (3*D_MODEL*D_MODEL/4)
#define NW_WO  (D_MODEL*D_MODEL/4)
#define NW_A   (NW_WQ + NW_WO)
#define NW_W1  (2*FF*D_MODEL/4)
#define NW_W2  (D_MODEL*FF/4)
#define NW_B   (NW_W1 + NW_W2)

__global__ void __launch_bounds__(256)
split_wA(const float* __restrict__ Wqkv, const float* __restrict__ Wout,
         __nv_bfloat16* __restrict__ wqh, __nv_bfloat16* __restrict__ wql,
         __nv_bfloat16* __restrict__ woh)
{
    int i = blockIdx.x * blockDim.x + threadIdx.x;
    if (i >= NW_A) return;
    if (i < NW_WQ) {
        float4 v = ((const float4*)Wqkv)[i];
        __nv_bfloat16 h[4], l[4];
        split2(v.x, h[0], l[0]); split2(v.y, h[1], l[1]);
        split2(v.z, h[2], l[2]); split2(v.w, h[3], l[3]);
        ((uint2*)wqh)[i] = *(uint2*)h;
        ((uint2*)wql)[i] = *(uint2*)l;
        return;
    }
    size_t o = i - NW_WQ;
    float4 v = ((const float4*)Wout)[o];
    __nv_bfloat16 h[4];
    h[0] = __float2bfloat16_rn(v.x); h[1] = __float2bfloat16_rn(v.y);
    h[2] = __float2bfloat16_rn(v.z); h[3] = __float2bfloat16_rn(v.w);
    ((uint2*)woh)[o] = *(uint2*)h;
}

__global__ void __launch_bounds__(256)
split_wB(const float* __restrict__ W1, const float* __restrict__ W2,
         __nv_bfloat16* __restrict__ w1h, __nv_bfloat16* __restrict__ w2h)
{
    int i = blockIdx.x * blockDim.x + threadIdx.x;
    if (i >= NW_B) return;
    if (i < NW_W1) {
        int flat = i * 4;
        int row = flat >> 10;
        int col = flat & (D_MODEL - 1);
        int prow = (row < FF) ? (2 * row) : (2 * (row - FF) + 1);
        float4 v = ((const float4*)W1)[i];
        __nv_bfloat16 h[4];
        h[0] = __float2bfloat16_rn(v.x); h[1] = __float2bfloat16_rn(v.y);
        h[2] = __float2bfloat16_rn(v.z); h[3] = __float2bfloat16_rn(v.w);
        ((uint2*)w1h)[((size_t)prow * D_MODEL + col) >> 2] = *(uint2*)h;
        return;
    }
    size_t o = i - NW_W1;
    float4 v = ((const float4*)W2)[o];
    __nv_bfloat16 h[4];
    h[0] = __float2bfloat16_rn(v.x); h[1] = __float2bfloat16_rn(v.y);
    h[2] = __float2bfloat16_rn(v.z); h[3] = __float2bfloat16_rn(v.w);
    ((uint2*)w2h)[o] = *(uint2*)h;
}

// ---------------- x split + rope table ----------------------------------------
#define NX_X   (MTOT*D_MODEL/4)
#define NX_ROPE (SEQ*32)
#define NX_TOTAL (NX_X + NX_ROPE)

__global__ void __launch_bounds__(256)
split_x_rope(const float* __restrict__ x,
             __nv_bfloat16* __restrict__ xh, __nv_bfloat16* __restrict__ xl,
             float* __restrict__ rope)
{
    int i = blockIdx.x * blockDim.x + threadIdx.x;
    if (i >= NX_TOTAL) return;
    if (i >= NX_X) {
        int j = i - NX_X;
        int t = j >> 5, dd = j & 31;
        float inv = powf(10000.0f, -(float)dd / 32.0f);
        float s, c;
        sincosf((float)t * inv, &s, &c);
        rope[t * 64 + dd]      = c;
        rope[t * 64 + 32 + dd] = s;
        return;
    }
    float4 v = ((const float4*)x)[i];
    __nv_bfloat16 h[4], l[4];
    split2(v.x, h[0], l[0]); split2(v.y, h[1], l[1]);
    split2(v.z, h[2], l[2]); split2(v.w, h[3], l[3]);
    ((uint2*)xh)[i] = *(uint2*)h;
    ((uint2*)xl)[i] = *(uint2*)l;
}

// ---------------- banded attention v5 ------------------------------------------
#define QTILE 64
#define NKMAX 320
#define PADK  324          // mult of 4: float4-aligned P rows, float2 KT rows
#define PADV  68           // mult of 4: float4 Q rows, float2 V rows
#define NCH2  5
#define ATTN_SMEM ((64*PADK + NKMAX*PADV + 64*PADV) * sizeof(float))

__global__ void __launch_bounds__(512)
attn_kernel(const float* __restrict__ qkv, const float* __restrict__ rope,
            __nv_bfloat16* __restrict__ OH, __nv_bfloat16* __restrict__ OL)
{
    extern __shared__ float sm[];
    float* KT = sm;                         // [64][PADK]; later P [64][PADK]
    float* Vs = sm + 64 * PADK;             // [NKMAX][PADV]
    float* Qs = Vs + NKMAX * PADV;          // [64][PADV]

    const int bh = blockIdx.y;
    const int b = bh >> 4, h = bh & 15;
    const int q0 = blockIdx.x * QTILE;
    const int klo = max(0, q0 - 127);
    const int khi = min(SEQ - 1, q0 + QTILE - 1 + 128);
    const int nk = khi - klo + 1;

    const int tid = threadIdx.x;

    for (int i = tid; i < nk * 32; i += 512) {
        int r = i >> 5, dd = i & 31;
        int t = klo + r;
        const float* base = qkv + (size_t)(b * SEQ + t) * (3 * D_MODEL) + h * HEAD_DIM;
        float c0 = rope[t * 64 + dd], s0 = rope[t * 64 + 32 + dd];
        float k1 = base[D_MODEL + dd], k2 = base[D_MODEL + 32 + dd];
        KT[dd * PADK + r]        = k1 * c0 - k2 * s0;
        KT[(dd + 32) * PADK + r] = k2 * c0 + k1 * s0;
        Vs[r * PADV + dd]        = base[2 * D_MODEL + dd];
        Vs[r * PADV + 32 + dd]   = base[2 * D_MODEL + 32 + dd];
    }
    for (int i = tid; i < 64 * 8; i += 512) {
        int dd = i >> 3, r = nk + (i & 7);
        if (r < NKMAX) KT[dd * PADK + r] = 0.f;
    }
    for (int i = tid; i < QTILE * 32; i += 512) {
        int r = i >> 5, dd = i & 31;
        int t = q0 + r;
        const float* base = qkv + (size_t)(b * SEQ + t) * (3 * D_MODEL) + h * HEAD_DIM;
        float c0 = rope[t * 64 + dd], s0 = rope[t * 64 + 32 + dd];
        float q1 = base[dd], q2 = base[32 + dd];
        Qs[r * PADV + dd]      = q1 * c0 - q2 * s0;
        Qs[r * PADV + 32 + dd] = q2 * c0 + q1 * s0;
    }
    __syncthreads();

    const int w = tid >> 5, lane = tid & 31;
    const int qloc = w * 4;
    const int qg0 = q0 + qloc;

    // ---- scores: lane owns key pair (c*64 + 2*lane, +1); Q via float4 ----
    float2 acc[4][NCH2];
#pragma unroll
    for (int j = 0; j < 4; j++)
#pragma unroll
        for (int c = 0; c < NCH2; c++) acc[j][c] = make_float2(0.f, 0.f);

    for (int db = 0; db < HEAD_DIM; db += 4) {
        float4 q4[4];
#pragma unroll
        for (int j = 0; j < 4; j++)
            q4[j] = *(const float4*)&Qs[(qloc + j) * PADV + db];
#pragma unroll
        for (int dd = 0; dd < 4; dd++) {
            float qa = GETC(q4[0], dd);
            float qb = GETC(q4[1], dd);
            float qc = GETC(q4[2], dd);
            float qd = GETC(q4[3], dd);
            const float2* kt = (const float2*)(KT + (db + dd) * PADK) + lane;
#pragma unroll
            for (int c = 0; c < NCH2; c++) {
                float2 kv = kt[c * 32];
                acc[0][c].x += qa * kv.x; acc[0][c].y += qa * kv.y;
                acc[1][c].x += qb * kv.x; acc[1][c].y += qb * kv.y;
                acc[2][c].x += qc * kv.x; acc[2][c].y += qc * kv.y;
                acc[3][c].x += qd * kv.x; acc[3][c].y += qd * kv.y;
            }
        }
    }

    // ---- mask + softmax (registers, MUFU-free) ----
    float inv[4];
#pragma unroll
    for (int j = 0; j < 4; j++) {
        const int qg = qg0 + j;
        const int lo = max(0, qg - 127) - klo;
        const int hi = min(SEQ - 1, qg + 128) - klo;
        float m = -1e30f;
#pragma unroll
        for (int c = 0; c < NCH2; c++) {
            int kg = c * 64 + 2 * lane;
            float sx = (kg     >= lo && kg     <= hi) ? acc[j][c].x * 0.125f : -1e30f;
            float sy = (kg + 1 >= lo && kg + 1 <= hi) ? acc[j][c].y * 0.125f : -1e30f;
            acc[j][c].x = sx; acc[j][c].y = sy;
            m = fmaxf(m, fmaxf(sx, sy));
        }
#pragma unroll
        for (int o = 16; o; o >>= 1) m = fmaxf(m, __shfl_xor_sync(0xffffffffu, m, o));
        float sum = 0.f;
#pragma unroll
        for (int c = 0; c < NCH2; c++) {
            float ex = fexp(acc[j][c].x - m);
            float ey = fexp(acc[j][c].y - m);
            acc[j][c].x = ex; acc[j][c].y = ey;
            sum += ex + ey;
        }
#pragma unroll
        for (int o = 16; o; o >>= 1) sum += __shfl_xor_sync(0xffffffffu, sum, o);
        inv[j] = frcp(sum);
    }

    // ---- write normalized P (float2) into KT region ----
    __syncthreads();
    float* P = KT;
#pragma unroll
    for (int j = 0; j < 4; j++) {
        float2* prow = (float2*)(P + (qloc + j) * PADK) + lane;
#pragma unroll
        for (int c = 0; c < NCH2; c++)
            prow[c * 32] = make_float2(acc[j][c].x * inv[j], acc[j][c].y * inv[j]);
    }
    __syncthreads();

    // ---- PV: lane owns dims (2*lane, 2*lane+1); P via float4, 4-key groups ---
    const int kstart = (max(0, qg0 - 127) - klo) & ~3;
    const int kend   = min(SEQ - 1, qg0 + 3 + 128) - klo;

    float ox0 = 0.f, oy0 = 0.f, ox1 = 0.f, oy1 = 0.f;
    float ox2 = 0.f, oy2 = 0.f, ox3 = 0.f, oy3 = 0.f;
    const float* p0 = P + (qloc + 0) * PADK;
    const float* p1 = P + (qloc + 1) * PADK;
    const float* p2 = P + (qloc + 2) * PADK;
    const float* p3 = P + (qloc + 3) * PADK;

    int k = kstart;
    for (; k + 3 <= kend; k += 4) {
        float2 v0 = *(const float2*)&Vs[(k + 0) * PADV + 2 * lane];
        float2 v1 = *(const float2*)&Vs[(k + 1) * PADV + 2 * lane];
        float2 v2 = *(const float2*)&Vs[(k + 2) * PADV + 2 * lane];
        float2 v3 = *(const float2*)&Vs[(k + 3) * PADV + 2 * lane];
        float4 a0 = *(const float4*)&p0[k];
        float4 a1 = *(const float4*)&p1[k];
        float4 a2 = *(const float4*)&p2[k];
        float4 a3 = *(const float4*)&p3[k];
        ox0 += a0.x * v0.x + a0.y * v1.x + a0.z * v2.x + a0.w * v3.x;
        oy0 += a0.x * v0.y + a0.y * v1.y + a0.z * v2.y + a0.w * v3.y;
        ox1 += a1.x * v0.x + a1.y * v1.x + a1.z * v2.x + a1.w * v3.x;
        oy1 += a1.x * v0.y + a1.y * v1.y + a1.z * v2.y + a1.w * v3.y;
        ox2 += a2.x * v0.x + a2.y * v1.x + a2.z * v2.x + a2.w * v3.x;
        oy2 += a2.x * v0.y + a2.y * v1.y + a2.z * v2.y + a2.w * v3.y;
        ox3 += a3.x * v0.x + a3.y * v1.x + a3.z * v2.x + a3.w * v3.x;
        oy3 += a3.x * v0.y + a3.y * v1.y + a3.z * v2.y + a3.w * v3.y;
    }
    for (; k <= kend; k++) {
        float2 va = *(const float2*)&Vs[k * PADV + 2 * lane];
        float a0 = p0[k], a1 = p1[k], a2 = p2[k], a3 = p3[k];
        ox0 += a0 * va.x; oy0 += a0 * va.y;
        ox1 += a1 * va.x; oy1 += a1 * va.y;
        ox2 += a2 * va.x; oy2 += a2 * va.y;
        ox3 += a3 * va.x; oy3 += a3 * va.y;
    }

    float oxv[4] = {ox0, ox1, ox2, ox3};
    float oyv[4] = {oy0, oy1, oy2, oy3};
#pragma unroll
    for (int j = 0; j < 4; j++) {
        size_t ob = ((size_t)(b * SEQ + qg0 + j)) * D_MODEL + h * HEAD_DIM + 2 * lane;
        __nv_bfloat16 hx, lx, hy, ly;
        split2(oxv[j], hx, lx);
        split2(oyv[j], hy, ly);
        __nv_bfloat162 hp; hp.x = hx; hp.y = hy;
        __nv_bfloat162 lp; lp.x = lx; lp.y = ly;
        *(__nv_bfloat162*)(OH + ob) = hp;
        *(__nv_bfloat162*)(OL + ob) = lp;
    }
}

// ---------------- residual + (opt bias) + RMSNorm (+opt bf16 split out) ------
__global__ void __launch_bounds__(256)
resid_rmsnorm(const float* __restrict__ A, const float* __restrict__ bias,
              const float* __restrict__ R, const float* __restrict__ g,
              float* __restrict__ out,
              __nv_bfloat16* __restrict__ outH, __nv_bfloat16* __restrict__ outL)
{
    const int row = blockIdx.x;
    const float* a = A + (size_t)row * D_MODEL;
    const float* r = R + (size_t)row * D_MODEL;

    float v[4];
    float ss = 0.f;
#pragma unroll
    for (int i = 0; i < 4; i++) {
        int c = threadIdx.x + i * 256;
        float x = a[c] + ALPHA * r[c];
        if (bias) x += bias[c];
        v[i] = x;
        ss += x * x;
    }
#pragma unroll
    for (int o = 16; o; o >>= 1) ss += __shfl_xor_sync(0xffffffffu, ss, o);

    __shared__ float ws[8];
    if ((threadIdx.x & 31) == 0) ws[threadIdx.x >> 5] = ss;
    __syncthreads();
    if (threadIdx.x < 32) {
        float t = (threadIdx.x < 8) ? ws[threadIdx.x] : 0.f;
#pragma unroll
        for (int o = 4; o; o >>= 1) t += __shfl_xor_sync(0xffffffffu, t, o);
        if (threadIdx.x == 0) ws[0] = t;
    }
    __syncthreads();
    const float rms = rsqrtf(ws[0] * (1.0f / D_MODEL) + EPS);

    float* orow = out + (size_t)row * D_MODEL;
#pragma unroll
    for (int i = 0; i < 4; i++) {
        int c = threadIdx.x + i * 256;
        float y = v[i] * rms * g[c];
        orow[c] = y;
        if (outH) {
            __nv_bfloat16 h, l;
            split2(y, h, l);
            outH[(size_t)row * D_MODEL + c] = h;
            outL[(size_t)row * D_MODEL + c] = l;
        }
    }
}

// ---------------- host orchestration -----------------------------------------
template<int MODE, int NTERMS>
static void launch_gemm(const __nv_bfloat16* Ah, const __nv_bfloat16* Al,
                        const __nv_bfloat16* Bh, const __nv_bfloat16* Bl,
                        float* C, __nv_bfloat16* Ho, __nv_bfloat16* Lo,
                        int M, int N, int K)
{
    const int stage = (NTERMS == 3 ? 4 : 3) * TAH;
    const int nstg  = (NTERMS == 3 ? 3 : 4);
    size_t smem = (size_t)nstg * stage;
    cudaFuncSetAttribute(gemm_mma<MODE, NTERMS>, cudaFuncAttributeMaxDynamicSharedMemorySize, (int)smem);
    dim3 grid(N / GBN, M / GBM);
    gemm_mma<MODE, NTERMS><<<grid, 256, smem>>>(Ah, Al, Bh, Bl, C, Ho, Lo, M, N, K);
}

extern "C" void kernel_launch(void* const* d_in, const int* in_sizes, int n_in,
                              void* d_out, int out_size)
{
    const float* x    = (const float*)d_in[0];
    const float* Wqkv = (const float*)d_in[1];
    const float* Wout = (const float*)d_in[2];
    const float* bout = (const float*)d_in[3];
    const float* W1   = (const float*)d_in[4];
    const float* W2   = (const float*)d_in[5];
    const float* g1   = (const float*)d_in[6];
    const float* g2   = (const float*)d_in[7];
    float* out = (float*)d_out;

    float *qkv, *Ap, *x2, *y2, *rope;
    cudaGetSymbolAddress((void**)&qkv,  g_qkv);
    cudaGetSymbolAddress((void**)&Ap,   g_a);
    cudaGetSymbolAddress((void**)&x2,   g_x2);
    cudaGetSymbolAddress((void**)&y2,   g_y2);
    cudaGetSymbolAddress((void**)&rope, g_rope);

    __nv_bfloat16 *xh,*xl,*oh,*ol,*x2h,*x2l,*hbh,*hbl,*wqh,*wql,*woh,*w1h,*w2h;
    cudaGetSymbolAddress((void**)&xh,  g_xh);  cudaGetSymbolAddress((void**)&xl,  g_xl);
    cudaGetSymbolAddress((void**)&oh,  g_oh);  cudaGetSymbolAddress((void**)&ol,  g_ol);
    cudaGetSymbolAddress((void**)&x2h, g_x2h); cudaGetSymbolAddress((void**)&x2l, g_x2l);
    cudaGetSymbolAddress((void**)&hbh, g_hbh); cudaGetSymbolAddress((void**)&hbl, g_hbl);
    cudaGetSymbolAddress((void**)&wqh, g_wqh); cudaGetSymbolAddress((void**)&wql, g_wql);
    cudaGetSymbolAddress((void**)&woh, g_woh);
    cudaGetSymbolAddress((void**)&w1h, g_w1h);
    cudaGetSymbolAddress((void**)&w2h, g_w2h);

    // 0) weight split A (Wqkv hi+lo, Wout hi)                          [launch 0]
    split_wA<<<(NW_A + 255) / 256, 256>>>(Wqkv, Wout, wqh, wql, woh);

    // 1) weight split B (W1 perm hi, W2 hi)                            [launch 1]
    split_wB<<<(NW_B + 255) / 256, 256>>>(W1, W2, w1h, w2h);

    // 2) x split + rope table                                          [launch 2]
    split_x_rope<<<(NX_TOTAL + 255) / 256, 256>>>(x, xh, xl, rope);

    // 3) QKV = X @ Wqkv^T  (3-term)                       [launch 3 -> profiled]
    launch_gemm<0, 3>(xh, xl, wqh, wql, qkv, nullptr, nullptr, MTOT, 3 * D_MODEL, D_MODEL);

    // 4) banded attention (rope fused) -> oh/ol                        [launch 4]
    {
        cudaFuncSetAttribute(attn_kernel, cudaFuncAttributeMaxDynamicSharedMemorySize, (int)ATTN_SMEM);
        dim3 grid(SEQ / QTILE, BATCH * NHEAD);
        attn_kernel<<<grid, 512, ATTN_SMEM>>>(qkv, rope, oh, ol);
    }

    // 5) A = O @ Wout^T  (2-term, 4-stage)                             [launch 5]
    launch_gemm<0, 2>(oh, ol, woh, nullptr, Ap, nullptr, nullptr, MTOT, D_MODEL, D_MODEL);

    // 6) x2 = rmsnorm(A + bout + ALPHA*x, g1) (+ bf16 split)           [launch 6]
    resid_rmsnorm<<<MTOT, 256>>>(Ap, bout, x, g1, x2, x2h, x2l);

    // 7) fused: [y|gate] = x2 @ W1perm^T, swiglu (2-term, 4-stage)     [launch 7]
    launch_gemm<1, 2>(x2h, x2l, w1h, nullptr, nullptr, hbh, hbl, MTOT, 2 * FF, D_MODEL);

    // 8) Y2 = H @ W2^T  (K = FF, 2-term, 4-stage)                      [launch 8]
    launch_gemm<0, 2>(hbh, hbl, w2h, nullptr, y2, nullptr, nullptr, MTOT, D_MODEL, FF);

    // 9) out = rmsnorm(Y2 + ALPHA*x2, g2)                              [launch 9]
    resid_rmsnorm<<<MTOT, 256>>>(y2, nullptr, x2, g2, out, nullptr, nullptr);
}

// round 16
// speedup vs baseline: 1.0887x; 1.0328x over previous
#include <cuda_runtime.h>
#include <cuda_bf16.h>
#include <math.h>
#include <stdint.h>

// ---------------- problem constants ----------------
#define D_MODEL 1024
#define NHEAD   16
#define HEAD_DIM 64
#define FF      4096
#define ALPHA   1.4142135f
#define EPS     1e-5f
#define BATCH   2
#define SEQ     2048
#define MTOT    (BATCH*SEQ)        // 4096 rows

// ---------------- scratch (device globals; no allocation allowed) ------------
__device__ float g_qkv[(size_t)MTOT * 3 * D_MODEL];
__device__ float g_a  [(size_t)MTOT * D_MODEL];
__device__ float g_x2 [(size_t)MTOT * D_MODEL];
__device__ float g_y2 [(size_t)MTOT * D_MODEL];
__device__ float g_rope[(size_t)SEQ * 64];                // cos[32] | sin[32] per t

// bf16 hi/lo split operands
__device__ __nv_bfloat16 g_xh [(size_t)MTOT * D_MODEL];
__device__ __nv_bfloat16 g_xl [(size_t)MTOT * D_MODEL];
__device__ __nv_bfloat16 g_oh [(size_t)MTOT * D_MODEL];
__device__ __nv_bfloat16 g_ol [(size_t)MTOT * D_MODEL];
__device__ __nv_bfloat16 g_x2h[(size_t)MTOT * D_MODEL];
__device__ __nv_bfloat16 g_x2l[(size_t)MTOT * D_MODEL];
__device__ __nv_bfloat16 g_hbh[(size_t)MTOT * FF];
__device__ __nv_bfloat16 g_hbl[(size_t)MTOT * FF];
__device__ __nv_bfloat16 g_wqh[(size_t)3*D_MODEL * D_MODEL];
__device__ __nv_bfloat16 g_wql[(size_t)3*D_MODEL * D_MODEL];
__device__ __nv_bfloat16 g_woh[(size_t)D_MODEL * D_MODEL];
__device__ __nv_bfloat16 g_w1h[(size_t)2*FF * D_MODEL];   // permuted y/gate interleave
__device__ __nv_bfloat16 g_w2h[(size_t)D_MODEL * FF];

// ---------------- PTX helpers -------------------------------------------------
__device__ __forceinline__ uint32_t smem_u32(const void* p) {
    uint32_t a;
    asm("{ .reg .u64 t; cvta.to.shared.u64 t, %1; cvt.u32.u64 %0, t; }" : "=r"(a) : "l"(p));
    return a;
}

#define CP_ASYNC16(dst, src) \
    asm volatile("cp.async.cg.shared.global [%0], [%1], 16;" :: "r"(dst), "l"(src) : "memory")
#define CP_COMMIT() asm volatile("cp.async.commit_group;" ::: "memory")

#define LDSM_X4(r0, r1, r2, r3, addr) \
    asm volatile("ldmatrix.sync.aligned.m8n8.x4.shared.b16 {%0,%1,%2,%3}, [%4];" \
        : "=r"(r0), "=r"(r1), "=r"(r2), "=r"(r3) : "r"(addr))

#define MMA_BF16(d, a, b0v, b1v) \
    asm volatile("mma.sync.aligned.m16n8k16.row.col.f32.bf16.bf16.f32 " \
        "{%0,%1,%2,%3}, {%4,%5,%6,%7}, {%8,%9}, {%0,%1,%2,%3};" \
        : "+f"((d)[0]), "+f"((d)[1]), "+f"((d)[2]), "+f"((d)[3]) \
        : "r"((a)[0]), "r"((a)[1]), "r"((a)[2]), "r"((a)[3]), "r"(b0v), "r"(b1v))

__device__ __forceinline__ void split2(float x, __nv_bfloat16& h, __nv_bfloat16& l) {
    h = __float2bfloat16_rn(x);
    l = __float2bfloat16_rn(x - __bfloat162float(h));
}

// MUFU-free exp: rel err ~2e-7, clamped
__device__ __forceinline__ float fexp(float x) {
    float t = x * 1.4426950408889634f;
    t = fminf(fmaxf(t, -126.f), 126.f);
    float fi = rintf(t);
    float f = t - fi;
    float p = 1.5403530393e-4f;
    p = p * f + 1.3333558146e-3f;
    p = p * f + 9.6181291076e-3f;
    p = p * f + 5.5504108664e-2f;
    p = p * f + 2.4022650696e-1f;
    p = p * f + 6.9314718056e-1f;
    p = p * f + 1.0f;
    int ei = (int)fi;
    return __int_as_float((uint32_t)(ei + 127) << 23) * p;
}

// MUFU-free reciprocal (Newton, 3 iters)
__device__ __forceinline__ float frcp(float d) {
    float r = __int_as_float(0x7EF311C3u - __float_as_int(d));
    r = r * (2.f - d * r);
    r = r * (2.f - d * r);
    r = r * (2.f - d * r);
    return r;
}

#define GETC(v, i) ((i) == 0 ? (v).x : (i) == 1 ? (v).y : (i) == 2 ? (v).z : (v).w)

// ---------------- HMMA GEMM, bf16 hi/lo, 128x128, 2 CTAs/SM -------------------
// (unchanged R15 champion)
#define GBM 128
#define GBN 128
#define GK  32
#define TAH (GBM*64)
#define TBH (GBN*64)

template<int MODE, int NTERMS>
__global__ void __launch_bounds__(256, 2)
gemm_mma(const __nv_bfloat16* __restrict__ Ah, const __nv_bfloat16* __restrict__ Al,
         const __nv_bfloat16* __restrict__ Bh, const __nv_bfloat16* __restrict__ Bl,
         float* __restrict__ C,
         __nv_bfloat16* __restrict__ Ho, __nv_bfloat16* __restrict__ Lo,
         int M, int N, int K)
{
    constexpr int STAGE_B = (NTERMS == 3 ? 4 : 3) * TAH;
    constexpr int NSTG    = (NTERMS == 3 ? 3 : 4);
    constexpr int PREF    = NSTG - 1;
    extern __shared__ __align__(128) char smem[];

    const int tid  = threadIdx.x;
    const int lane = tid & 31;
    const int wid  = tid >> 5;
    const int wm   = wid >> 2;
    const int wn   = wid & 3;
    const int bm   = blockIdx.y * GBM;
    const int bn   = blockIdx.x * GBN;

    const int NK = K / GK;
    const uint32_t sbase = smem_u32(smem);

    const int lrow = tid >> 2;
    const int lcc  = tid & 3;

    auto load_stage = [&](int s, int kc) {
        const uint32_t st = sbase + s * STAGE_B;
#pragma unroll
        for (int half = 0; half < 2; half++) {
            const int row = lrow + half * 64;
            const uint32_t swz = (uint32_t)(row * 64 + ((lcc ^ ((row >> 1) & 3)) << 4));
            const size_t ao = (size_t)(bm + row) * K + kc * GK + lcc * 8;
            const size_t bo = (size_t)(bn + row) * K + kc * GK + lcc * 8;
            CP_ASYNC16(st + swz,               Ah + ao);
            CP_ASYNC16(st + TAH + swz,         Al + ao);
            CP_ASYNC16(st + 2*TAH + swz,       Bh + bo);
            if (NTERMS == 3)
                CP_ASYNC16(st + 3*TAH + swz,   Bl + bo);
        }
    };

    float acc[4][4][4];
#pragma unroll
    for (int mi = 0; mi < 4; mi++)
#pragma unroll
        for (int ni = 0; ni < 4; ni++)
#pragma unroll
            for (int r = 0; r < 4; r++) acc[mi][ni][r] = 0.f;

#pragma unroll
    for (int s = 0; s < PREF; s++) { load_stage(s, s); CP_COMMIT(); }

    const int m_idx = lane >> 3;
    int scur = 0, sload = PREF;

    for (int c = 0; c < NK; c++) {
        if (NSTG == 4)
            asm volatile("cp.async.wait_group 2;" ::: "memory");
        else
            asm volatile("cp.async.wait_group 1;" ::: "memory");
        __syncthreads();
        if (c + PREF < NK) load_stage(sload, c + PREF);
        CP_COMMIT();
        if (++sload == NSTG) sload = 0;

        const uint32_t st = sbase + scur * STAGE_B;
        if (++scur == NSTG) scur = 0;

#pragma unroll
        for (int ks = 0; ks < 2; ks++) {
            uint32_t afh[4][4], afl[4][4], bfh[2][4], bfl[2][4];
#pragma unroll
            for (int mi = 0; mi < 4; mi++) {
                const int row = wm * 64 + mi * 16 + (lane & 7) + ((m_idx & 1) << 3);
                const int cch = 2 * ks + (m_idx >> 1);
                const uint32_t off = (uint32_t)(row * 64 + ((cch ^ ((row >> 1) & 3)) << 4));
                LDSM_X4(afh[mi][0], afh[mi][1], afh[mi][2], afh[mi][3], st + off);
                LDSM_X4(afl[mi][0], afl[mi][1], afl[mi][2], afl[mi][3], st + TAH + off);
            }
#pragma unroll
            for (int pi = 0; pi < 2; pi++) {
                const int nrow = wn * 32 + pi * 16 + (lane & 7) + ((m_idx >> 1) << 3);
                const int cch = 2 * ks + (m_idx & 1);
                const uint32_t off = (uint32_t)(nrow * 64 + ((cch ^ ((nrow >> 1) & 3)) << 4));
                LDSM_X4(bfh[pi][0], bfh[pi][1], bfh[pi][2], bfh[pi][3], st + 2*TAH + off);
                if (NTERMS == 3)
                    LDSM_X4(bfl[pi][0], bfl[pi][1], bfl[pi][2], bfl[pi][3], st + 2*TAH + TBH + off);
            }
#pragma unroll
            for (int mi = 0; mi < 4; mi++)
#pragma unroll
                for (int ni = 0; ni < 4; ni++)
                    MMA_BF16(acc[mi][ni], afh[mi],
                             bfh[ni >> 1][(ni & 1) * 2], bfh[ni >> 1][(ni & 1) * 2 + 1]);
#pragma unroll
            for (int mi = 0; mi < 4; mi++)
#pragma unroll
                for (int ni = 0; ni < 4; ni++)
                    MMA_BF16(acc[mi][ni], afl[mi],
                             bfh[ni >> 1][(ni & 1) * 2], bfh[ni >> 1][(ni & 1) * 2 + 1]);
            if (NTERMS == 3) {
#pragma unroll
                for (int mi = 0; mi < 4; mi++)
#pragma unroll
                    for (int ni = 0; ni < 4; ni++)
                        MMA_BF16(acc[mi][ni], afh[mi],
                                 bfl[ni >> 1][(ni & 1) * 2], bfl[ni >> 1][(ni & 1) * 2 + 1]);
            }
        }
    }

#pragma unroll
    for (int mi = 0; mi < 4; mi++) {
        const int row0 = bm + wm * 64 + mi * 16 + (lane >> 2);
#pragma unroll
        for (int ni = 0; ni < 4; ni++) {
            const int col = bn + wn * 32 + ni * 8 + (lane & 3) * 2;
            if (MODE == 0) {
                *(float2*)(C + (size_t)row0 * N + col)       = make_float2(acc[mi][ni][0], acc[mi][ni][1]);
                *(float2*)(C + (size_t)(row0 + 8) * N + col) = make_float2(acc[mi][ni][2], acc[mi][ni][3]);
            } else {
                const int Nout = N >> 1;
                const int j = col >> 1;
                float y0 = acc[mi][ni][0], gt0 = acc[mi][ni][1];
                float y1 = acc[mi][ni][2], gt1 = acc[mi][ni][3];
                float h0 = y0 * gt0 * frcp(1.f + fexp(-gt0));
                float h1 = y1 * gt1 * frcp(1.f + fexp(-gt1));
                __nv_bfloat16 hh, ll;
                split2(h0, hh, ll);
                Ho[(size_t)row0 * Nout + j] = hh;
                Lo[(size_t)row0 * Nout + j] = ll;
                split2(h1, hh, ll);
                Ho[(size_t)(row0 + 8) * Nout + j] = hh;
                Lo[(size_t)(row0 + 8) * Nout + j] = ll;
            }
        }
    }
}

// ---------------- weight splits -----------------------------------------------
#define NW_WQ  (3*D_MODEL*D_MODEL/4)
#define NW_WO  (D_MODEL*D_MODEL/4)
#define NW_A   (NW_WQ + NW_WO)
#define NW_W1  (2*FF*D_MODEL/4)
#define NW_W2  (D_MODEL*FF/4)
#define NW_B   (NW_W1 + NW_W2)

__global__ void __launch_bounds__(256)
split_wA(const float* __restrict__ Wqkv, const float* __restrict__ Wout,
         __nv_bfloat16* __restrict__ wqh, __nv_bfloat16* __restrict__ wql,
         __nv_bfloat16* __restrict__ woh)
{
    int i = blockIdx.x * blockDim.x + threadIdx.x;
    if (i >= NW_A) return;
    if (i < NW_WQ) {
        float4 v = ((const float4*)Wqkv)[i];
        __nv_bfloat16 h[4], l[4];
        split2(v.x, h[0], l[0]); split2(v.y, h[1], l[1]);
        split2(v.z, h[2], l[2]); split2(v.w, h[3], l[3]);
        ((uint2*)wqh)[i] = *(uint2*)h;
        ((uint2*)wql)[i] = *(uint2*)l;
        return;
    }
    size_t o = i - NW_WQ;
    float4 v = ((const float4*)Wout)[o];
    __nv_bfloat16 h[4];
    h[0] = __float2bfloat16_rn(v.x); h[1] = __float2bfloat16_rn(v.y);
    h[2] = __float2bfloat16_rn(v.z); h[3] = __float2bfloat16_rn(v.w);
    ((uint2*)woh)[o] = *(uint2*)h;
}

__global__ void __launch_bounds__(256)
split_wB(const float* __restrict__ W1, const float* __restrict__ W2,
         __nv_bfloat16* __restrict__ w1h, __nv_bfloat16* __restrict__ w2h)
{
    int i = blockIdx.x * blockDim.x + threadIdx.x;
    if (i >= NW_B) return;
    if (i < NW_W1) {
        int flat = i * 4;
        int row = flat >> 10;
        int col = flat & (D_MODEL - 1);
        int prow = (row < FF) ? (2 * row) : (2 * (row - FF) + 1);
        float4 v = ((const float4*)W1)[i];
        __nv_bfloat16 h[4];
        h[0] = __float2bfloat16_rn(v.x); h[1] = __float2bfloat16_rn(v.y);
        h[2] = __float2bfloat16_rn(v.z); h[3] = __float2bfloat16_rn(v.w);
        ((uint2*)w1h)[((size_t)prow * D_MODEL + col) >> 2] = *(uint2*)h;
        return;
    }
    size_t o = i - NW_W1;
    float4 v = ((const float4*)W2)[o];
    __nv_bfloat16 h[4];
    h[0] = __float2bfloat16_rn(v.x); h[1] = __float2bfloat16_rn(v.y);
    h[2] = __float2bfloat16_rn(v.z); h[3] = __float2bfloat16_rn(v.w);
    ((uint2*)w2h)[o] = *(uint2*)h;
}

// ---------------- x split + rope table ----------------------------------------
#define NX_X   (MTOT*D_MODEL/4)
#define NX_ROPE (SEQ*32)
#define NX_TOTAL (NX_X + NX_ROPE)

__global__ void __launch_bounds__(256)
split_x_rope(const float* __restrict__ x,
             __nv_bfloat16* __restrict__ xh, __nv_bfloat16* __restrict__ xl,
             float* __restrict__ rope)
{
    int i = blockIdx.x * blockDim.x + threadIdx.x;
    if (i >= NX_TOTAL) return;
    if (i >= NX_X) {
        int j = i - NX_X;
        int t = j >> 5, dd = j & 31;
        float inv = powf(10000.0f, -(float)dd / 32.0f);
        float s, c;
        sincosf((float)t * inv, &s, &c);
        rope[t * 64 + dd]      = c;
        rope[t * 64 + 32 + dd] = s;
        return;
    }
    float4 v = ((const float4*)x)[i];
    __nv_bfloat16 h[4], l[4];
    split2(v.x, h[0], l[0]); split2(v.y, h[1], l[1]);
    split2(v.z, h[2], l[2]); split2(v.w, h[3], l[3]);
    ((uint2*)xh)[i] = *(uint2*)h;
    ((uint2*)xl)[i] = *(uint2*)l;
}

// ---------------- banded attention v6: HMMA score pass -------------------------
// Smem: Kh/Kl bf16 [320][72] (144B pitch; region reused as S fp32 [64][PADS]),
//       Qh/Ql bf16 [64][72], Vs fp32 [320][PADV]. 512 threads, 16 warps.
#define QTILE 64
#define NKMAX 320
#define QKPITCH 72          // bf16 elems per row (144 B: conflict-free ldmatrix)
#define PADS  324
#define PADV  68
#define NCH2  5
#define OFF_KL 46080
#define OFF_QH 92160
#define OFF_QL 101376
#define OFF_V  110592
#define ATTN_SMEM (OFF_V + NKMAX*PADV*4)

__global__ void __launch_bounds__(512)
attn_kernel(const float* __restrict__ qkv, const float* __restrict__ rope,
            __nv_bfloat16* __restrict__ OH, __nv_bfloat16* __restrict__ OL)
{
    extern __shared__ __align__(128) char smc[];
    __nv_bfloat16* KhP = (__nv_bfloat16*)(smc);
    __nv_bfloat16* KlP = (__nv_bfloat16*)(smc + OFF_KL);
    __nv_bfloat16* QhP = (__nv_bfloat16*)(smc + OFF_QH);
    __nv_bfloat16* QlP = (__nv_bfloat16*)(smc + OFF_QL);
    float* Vs = (float*)(smc + OFF_V);
    float* S  = (float*)smc;                       // aliases K region after scores
    const uint32_t sb = smem_u32(smc);

    const int bh = blockIdx.y;
    const int b = bh >> 4, h = bh & 15;
    const int q0 = blockIdx.x * QTILE;
    const int klo = max(0, q0 - 127);
    const int khi = min(SEQ - 1, q0 + QTILE - 1 + 128);
    const int nk = khi - klo + 1;

    const int tid = threadIdx.x;

    // ---- load K (rope'd, bf16 h/l) + V (fp32) ----
    for (int i = tid; i < nk * 32; i += 512) {
        int r = i >> 5, dd = i & 31;
        int t = klo + r;
        const float* base = qkv + (size_t)(b * SEQ + t) * (3 * D_MODEL) + h * HEAD_DIM;
        float c0 = rope[t * 64 + dd], s0 = rope[t * 64 + 32 + dd];
        float k1 = base[D_MODEL + dd], k2 = base[D_MODEL + 32 + dd];
        float kr1 = k1 * c0 - k2 * s0;
        float kr2 = k2 * c0 + k1 * s0;
        __nv_bfloat16 hh, ll;
        split2(kr1, hh, ll);
        KhP[r * QKPITCH + dd] = hh;      KlP[r * QKPITCH + dd] = ll;
        split2(kr2, hh, ll);
        KhP[r * QKPITCH + 32 + dd] = hh; KlP[r * QKPITCH + 32 + dd] = ll;
        Vs[r * PADV + dd]      = base[2 * D_MODEL + dd];
        Vs[r * PADV + 32 + dd] = base[2 * D_MODEL + 32 + dd];
    }
    // zero K rows beyond nk (keep MMA inputs finite)
    for (int i = tid; i < (NKMAX - nk) * 64; i += 512) {
        int r = nk + (i >> 6), d = i & 63;
        KhP[r * QKPITCH + d] = __float2bfloat16_rn(0.f);
        KlP[r * QKPITCH + d] = __float2bfloat16_rn(0.f);
    }
    // ---- load Q (rope'd, bf16 h/l) ----
    for (int i = tid; i < QTILE * 32; i += 512) {
        int r = i >> 5, dd = i & 31;
        int t = q0 + r;
        const float* base = qkv + (size_t)(b * SEQ + t) * (3 * D_MODEL) + h * HEAD_DIM;
        float c0 = rope[t * 64 + dd], s0 = rope[t * 64 + 32 + dd];
        float q1 = base[dd], q2 = base[32 + dd];
        __nv_bfloat16 hh, ll;
        split2(q1 * c0 - q2 * s0, hh, ll);
        QhP[r * QKPITCH + dd] = hh;      QlP[r * QKPITCH + dd] = ll;
        split2(q2 * c0 + q1 * s0, hh, ll);
        QhP[r * QKPITCH + 32 + dd] = hh; QlP[r * QKPITCH + 32 + dd] = ll;
    }
    __syncthreads();

    const int w = tid >> 5, lane = tid & 31;
    const int m_idx = lane >> 3;

    // ---- score pass via HMMA: warp w -> S[qtile..+16][keybase..+80] ----
    {
        const int qtile = (w >> 2) * 16;
        const int keybase = (w & 3) * 80;
        float sacc[10][4];
#pragma unroll
        for (int ni = 0; ni < 10; ni++)
#pragma unroll
            for (int r = 0; r < 4; r++) sacc[ni][r] = 0.f;

        const int arow = qtile + (lane & 7) + ((m_idx & 1) << 3);
        const int brow = keybase + (lane & 7) + ((m_idx >> 1) << 3);
#pragma unroll
        for (int dc = 0; dc < 4; dc++) {
            const uint32_t aoff = (uint32_t)(arow * 144 + (2 * dc + (m_idx >> 1)) * 16);
            uint32_t ah[4], al[4];
            LDSM_X4(ah[0], ah[1], ah[2], ah[3], sb + OFF_QH + aoff);
            LDSM_X4(al[0], al[1], al[2], al[3], sb + OFF_QL + aoff);
            const uint32_t bk = (uint32_t)((2 * dc + (m_idx & 1)) * 16);
#pragma unroll
            for (int pp = 0; pp < 5; pp++) {
                const uint32_t boff = (uint32_t)((brow + pp * 16) * 144) + bk;
                uint32_t bhr[4], blr[4];
                LDSM_X4(bhr[0], bhr[1], bhr[2], bhr[3], sb + boff);
                LDSM_X4(blr[0], blr[1], blr[2], blr[3], sb + OFF_KL + boff);
                MMA_BF16(sacc[2*pp],     ah, bhr[0], bhr[1]);
                MMA_BF16(sacc[2*pp + 1], ah, bhr[2], bhr[3]);
                MMA_BF16(sacc[2*pp],     al, bhr[0], bhr[1]);
                MMA_BF16(sacc[2*pp + 1], al, bhr[2], bhr[3]);
                MMA_BF16(sacc[2*pp],     ah, blr[0], blr[1]);
                MMA_BF16(sacc[2*pp + 1], ah, blr[2], blr[3]);
            }
        }
        __syncthreads();        // all K/Q ldmatrix reads complete before S overwrite
        const int srow = qtile + (lane >> 2);
#pragma unroll
        for (int ni = 0; ni < 10; ni++) {
            const int key = keybase + ni * 8 + (lane & 3) * 2;
            *(float2*)&S[srow * PADS + key]       = make_float2(sacc[ni][0], sacc[ni][1]);
            *(float2*)&S[(srow + 8) * PADS + key] = make_float2(sacc[ni][2], sacc[ni][3]);
        }
    }
    __syncthreads();

    // ---- softmax: warp w owns rows qloc..qloc+3 (reads/writes exclusive) ----
    const int qloc = w * 4;
    const int qg0 = q0 + qloc;

    float2 acc[4][NCH2];
#pragma unroll
    for (int j = 0; j < 4; j++)
#pragma unroll
        for (int c = 0; c < NCH2; c++)
            acc[j][c] = *(const float2*)&S[(qloc + j) * PADS + c * 64 + 2 * lane];

    float inv[4];
#pragma unroll
    for (int j = 0; j < 4; j++) {
        const int qg = qg0 + j;
        const int lo = max(0, qg - 127) - klo;
        const int hi = min(SEQ - 1, qg + 128) - klo;
        float m = -1e30f;
#pragma unroll
        for (int c = 0; c < NCH2; c++) {
            int kg = c * 64 + 2 * lane;
            float sx = (kg     >= lo && kg     <= hi) ? acc[j][c].x * 0.125f : -1e30f;
            float sy = (kg + 1 >= lo && kg + 1 <= hi) ? acc[j][c].y * 0.125f : -1e30f;
            acc[j][c].x = sx; acc[j][c].y = sy;
            m = fmaxf(m, fmaxf(sx, sy));
        }
#pragma unroll
        for (int o = 16; o; o >>= 1) m = fmaxf(m, __shfl_xor_sync(0xffffffffu, m, o));
        float sum = 0.f;
#pragma unroll
        for (int c = 0; c < NCH2; c++) {
            float ex = fexp(acc[j][c].x - m);
            float ey = fexp(acc[j][c].y - m);
            acc[j][c].x = ex; acc[j][c].y = ey;
            sum += ex + ey;
        }
#pragma unroll
        for (int o = 16; o; o >>= 1) sum += __shfl_xor_sync(0xffffffffu, sum, o);
        inv[j] = frcp(sum);
    }

    // write normalized P in place over S (rows exclusive per warp)
    float* P = S;
#pragma unroll
    for (int j = 0; j < 4; j++) {
        float2* prow = (float2*)(P + (qloc + j) * PADS) + lane;
#pragma unroll
        for (int c = 0; c < NCH2; c++)
            prow[c * 32] = make_float2(acc[j][c].x * inv[j], acc[j][c].y * inv[j]);
    }
    __syncthreads();

    // ---- PV: lane owns dims (2*lane, 2*lane+1); P via float4, 4-key groups ---
    const int kstart = (max(0, qg0 - 127) - klo) & ~3;
    const int kend   = min(SEQ - 1, qg0 + 3 + 128) - klo;

    float ox0 = 0.f, oy0 = 0.f, ox1 = 0.f, oy1 = 0.f;
    float ox2 = 0.f, oy2 = 0.f, ox3 = 0.f, oy3 = 0.f;
    const float* p0 = P + (qloc + 0) * PADS;
    const float* p1 = P + (qloc + 1) * PADS;
    const float* p2 = P + (qloc + 2) * PADS;
    const float* p3 = P + (qloc + 3) * PADS;

    int k = kstart;
    for (; k + 3 <= kend; k += 4) {
        float2 v0 = *(const float2*)&Vs[(k + 0) * PADV + 2 * lane];
        float2 v1 = *(const float2*)&Vs[(k + 1) * PADV + 2 * lane];
        float2 v2 = *(const float2*)&Vs[(k + 2) * PADV + 2 * lane];
        float2 v3 = *(const float2*)&Vs[(k + 3) * PADV + 2 * lane];
        float4 a0 = *(const float4*)&p0[k];
        float4 a1 = *(const float4*)&p1[k];
        float4 a2 = *(const float4*)&p2[k];
        float4 a3 = *(const float4*)&p3[k];
        ox0 += a0.x * v0.x + a0.y * v1.x + a0.z * v2.x + a0.w * v3.x;
        oy0 += a0.x * v0.y + a0.y * v1.y + a0.z * v2.y + a0.w * v3.y;
        ox1 += a1.x * v0.x + a1.y * v1.x + a1.z * v2.x + a1.w * v3.x;
        oy1 += a1.x * v0.y + a1.y * v1.y + a1.z * v2.y + a1.w * v3.y;
        ox2 += a2.x * v0.x + a2.y * v1.x + a2.z * v2.x + a2.w * v3.x;
        oy2 += a2.x * v0.y + a2.y * v1.y + a2.z * v2.y + a2.w * v3.y;
        ox3 += a3.x * v0.x + a3.y * v1.x + a3.z * v2.x + a3.w * v3.x;
        oy3 += a3.x * v0.y + a3.y * v1.y + a3.z * v2.y + a3.w * v3.y;
    }
    for (; k <= kend; k++) {
        float2 va = *(const float2*)&Vs[k * PADV + 2 * lane];
        float a0 = p0[k], a1 = p1[k], a2 = p2[k], a3 = p3[k];
        ox0 += a0 * va.x; oy0 += a0 * va.y;
        ox1 += a1 * va.x; oy1 += a1 * va.y;
        ox2 += a2 * va.x; oy2 += a2 * va.y;
        ox3 += a3 * va.x; oy3 += a3 * va.y;
    }

    float oxv[4] = {ox0, ox1, ox2, ox3};
    float oyv[4] = {oy0, oy1, oy2, oy3};
#pragma unroll
    for (int j = 0; j < 4; j++) {
        size_t ob = ((size_t)(b * SEQ + qg0 + j)) * D_MODEL + h * HEAD_DIM + 2 * lane;
        __nv_bfloat16 hx, lx, hy, ly;
        split2(oxv[j], hx, lx);
        split2(oyv[j], hy, ly);
        __nv_bfloat162 hp; hp.x = hx; hp.y = hy;
        __nv_bfloat162 lp; lp.x = lx; lp.y = ly;
        *(__nv_bfloat162*)(OH + ob) = hp;
        *(__nv_bfloat162*)(OL + ob) = lp;
    }
}

// ---------------- residual + (opt bias) + RMSNorm (+opt bf16 split out) ------
__global__ void __launch_bounds__(256)
resid_rmsnorm(const float* __restrict__ A, const float* __restrict__ bias,
              const float* __restrict__ R, const float* __restrict__ g,
              float* __restrict__ out,
              __nv_bfloat16* __restrict__ outH, __nv_bfloat16* __restrict__ outL)
{
    const int row = blockIdx.x;
    const float* a = A + (size_t)row * D_MODEL;
    const float* r = R + (size_t)row * D_MODEL;

    float v[4];
    float ss = 0.f;
#pragma unroll
    for (int i = 0; i < 4; i++) {
        int c = threadIdx.x + i * 256;
        float x = a[c] + ALPHA * r[c];
        if (bias) x += bias[c];
        v[i] = x;
        ss += x * x;
    }
#pragma unroll
    for (int o = 16; o; o >>= 1) ss += __shfl_xor_sync(0xffffffffu, ss, o);

    __shared__ float ws[8];
    if ((threadIdx.x & 31) == 0) ws[threadIdx.x >> 5] = ss;
    __syncthreads();
    if (threadIdx.x < 32) {
        float t = (threadIdx.x < 8) ? ws[threadIdx.x] : 0.f;
#pragma unroll
        for (int o = 4; o; o >>= 1) t += __shfl_xor_sync(0xffffffffu, t, o);
        if (threadIdx.x == 0) ws[0] = t;
    }
    __syncthreads();
    const float rms = rsqrtf(ws[0] * (1.0f / D_MODEL) + EPS);

    float* orow = out + (size_t)row * D_MODEL;
#pragma unroll
    for (int i = 0; i < 4; i++) {
        int c = threadIdx.x + i * 256;
        float y = v[i] * rms * g[c];
        orow[c] = y;
        if (outH) {
            __nv_bfloat16 h, l;
            split2(y, h, l);
            outH[(size_t)row * D_MODEL + c] = h;
            outL[(size_t)row * D_MODEL + c] = l;
        }
    }
}

// ---------------- host orchestration -----------------------------------------
template<int MODE, int NTERMS>
static void launch_gemm(const __nv_bfloat16* Ah, const __nv_bfloat16* Al,
                        const __nv_bfloat16* Bh, const __nv_bfloat16* Bl,
                        float* C, __nv_bfloat16* Ho, __nv_bfloat16* Lo,
                        int M, int N, int K)
{
    const int stage = (NTERMS == 3 ? 4 : 3) * TAH;
    const int nstg  = (NTERMS == 3 ? 3 : 4);
    size_t smem = (size_t)nstg * stage;
    cudaFuncSetAttribute(gemm_mma<MODE, NTERMS>, cudaFuncAttributeMaxDynamicSharedMemorySize, (int)smem);
    dim3 grid(N / GBN, M / GBM);
    gemm_mma<MODE, NTERMS><<<grid, 256, smem>>>(Ah, Al, Bh, Bl, C, Ho, Lo, M, N, K);
}

extern "C" void kernel_launch(void* const* d_in, const int* in_sizes, int n_in,
                              void* d_out, int out_size)
{
    const float* x    = (const float*)d_in[0];
    const float* Wqkv = (const float*)d_in[1];
    const float* Wout = (const float*)d_in[2];
    const float* bout = (const float*)d_in[3];
    const float* W1   = (const float*)d_in[4];
    const float* W2   = (const float*)d_in[5];
    const float* g1   = (const float*)d_in[6];
    const float* g2   = (const float*)d_in[7];
    float* out = (float*)d_out;

    float *qkv, *Ap, *x2, *y2, *rope;
    cudaGetSymbolAddress((void**)&qkv,  g_qkv);
    cudaGetSymbolAddress((void**)&Ap,   g_a);
    cudaGetSymbolAddress((void**)&x2,   g_x2);
    cudaGetSymbolAddress((void**)&y2,   g_y2);
    cudaGetSymbolAddress((void**)&rope, g_rope);

    __nv_bfloat16 *xh,*xl,*oh,*ol,*x2h,*x2l,*hbh,*hbl,*wqh,*wql,*woh,*w1h,*w2h;
    cudaGetSymbolAddress((void**)&xh,  g_xh);  cudaGetSymbolAddress((void**)&xl,  g_xl);
    cudaGetSymbolAddress((void**)&oh,  g_oh);  cudaGetSymbolAddress((void**)&ol,  g_ol);
    cudaGetSymbolAddress((void**)&x2h, g_x2h); cudaGetSymbolAddress((void**)&x2l, g_x2l);
    cudaGetSymbolAddress((void**)&hbh, g_hbh); cudaGetSymbolAddress((void**)&hbl, g_hbl);
    cudaGetSymbolAddress((void**)&wqh, g_wqh); cudaGetSymbolAddress((void**)&wql, g_wql);
    cudaGetSymbolAddress((void**)&woh, g_woh);
    cudaGetSymbolAddress((void**)&w1h, g_w1h);
    cudaGetSymbolAddress((void**)&w2h, g_w2h);

    // 0) weight split A (Wqkv hi+lo, Wout hi)                          [launch 0]
    split_wA<<<(NW_A + 255) / 256, 256>>>(Wqkv, Wout, wqh, wql, woh);

    // 1) weight split B (W1 perm hi, W2 hi)                            [launch 1]
    split_wB<<<(NW_B + 255) / 256, 256>>>(W1, W2, w1h, w2h);

    // 2) x split + rope table                                          [launch 2]
    split_x_rope<<<(NX_TOTAL + 255) / 256, 256>>>(x, xh, xl, rope);

    // 3) QKV = X @ Wqkv^T  (3-term)                       [launch 3 -> profiled]
    launch_gemm<0, 3>(xh, xl, wqh, wql, qkv, nullptr, nullptr, MTOT, 3 * D_MODEL, D_MODEL);

    // 4) banded attention (rope fused, HMMA scores) -> oh/ol           [launch 4]
    {
        cudaFuncSetAttribute(attn_kernel, cudaFuncAttributeMaxDynamicSharedMemorySize, (int)ATTN_SMEM);
        dim3 grid(SEQ / QTILE, BATCH * NHEAD);
        attn_kernel<<<grid, 512, ATTN_SMEM>>>(qkv, rope, oh, ol);
    }

    // 5) A = O @ Wout^T  (2-term, 4-stage)                             [launch 5]
    launch_gemm<0, 2>(oh, ol, woh, nullptr, Ap, nullptr, nullptr, MTOT, D_MODEL, D_MODEL);

    // 6) x2 = rmsnorm(A + bout + ALPHA*x, g1) (+ bf16 split)           [launch 6]
    resid_rmsnorm<<<MTOT, 256>>>(Ap, bout, x, g1, x2, x2h, x2l);

    // 7) fused: [y|gate] = x2 @ W1perm^T, swiglu (2-term, 4-stage)     [launch 7]
    launch_gemm<1, 2>(x2h, x2l, w1h, nullptr, nullptr, hbh, hbl, MTOT, 2 * FF, D_MODEL);

    // 8) Y2 = H @ W2^T  (K = FF, 2-term, 4-stage)                      [launch 8]
    launch_gemm<0, 2>(hbh, hbl, w2h, nullptr, y2, nullptr, nullptr, MTOT, D_MODEL, FF);

    // 9) out = rmsnorm(Y2 + ALPHA*x2, g2)                              [launch 9]
    resid_rmsnorm<<<MTOT, 256>>>(y2, nullptr, x2, g2, out, nullptr, nullptr);
}

// round 17
// speedup vs baseline: 1.1244x; 1.0328x over previous
#include <cuda_runtime.h>
#include <cuda_bf16.h>
#include <math.h>
#include <stdint.h>

// ---------------- problem constants ----------------
#define D_MODEL 1024
#define NHEAD   16
#define HEAD_DIM 64
#define FF      4096
#define ALPHA   1.4142135f
#define EPS     1e-5f
#define BATCH   2
#define SEQ     2048
#define MTOT    (BATCH*SEQ)        // 4096 rows

// ---------------- scratch (device globals; no allocation allowed) ------------
__device__ float g_qkv[(size_t)MTOT * 3 * D_MODEL];
__device__ float g_a  [(size_t)MTOT * D_MODEL];
__device__ float g_x2 [(size_t)MTOT * D_MODEL];
__device__ float g_y2 [(size_t)MTOT * D_MODEL];
__device__ float g_rope[(size_t)SEQ * 64];                // cos[32] | sin[32] per t

// bf16 hi/lo split operands
__device__ __nv_bfloat16 g_xh [(size_t)MTOT * D_MODEL];
__device__ __nv_bfloat16 g_xl [(size_t)MTOT * D_MODEL];
__device__ __nv_bfloat16 g_oh [(size_t)MTOT * D_MODEL];
__device__ __nv_bfloat16 g_ol [(size_t)MTOT * D_MODEL];
__device__ __nv_bfloat16 g_x2h[(size_t)MTOT * D_MODEL];
__device__ __nv_bfloat16 g_x2l[(size_t)MTOT * D_MODEL];
__device__ __nv_bfloat16 g_hbh[(size_t)MTOT * FF];
__device__ __nv_bfloat16 g_hbl[(size_t)MTOT * FF];
__device__ __nv_bfloat16 g_wqh[(size_t)3*D_MODEL * D_MODEL];
__device__ __nv_bfloat16 g_wql[(size_t)3*D_MODEL * D_MODEL];
__device__ __nv_bfloat16 g_woh[(size_t)D_MODEL * D_MODEL];
__device__ __nv_bfloat16 g_w1h[(size_t)2*FF * D_MODEL];   // permuted y/gate interleave
__device__ __nv_bfloat16 g_w2h[(size_t)D_MODEL * FF];

// ---------------- PTX helpers -------------------------------------------------
__device__ __forceinline__ uint32_t smem_u32(const void* p) {
    uint32_t a;
    asm("{ .reg .u64 t; cvta.to.shared.u64 t, %1; cvt.u32.u64 %0, t; }" : "=r"(a) : "l"(p));
    return a;
}

#define CP_ASYNC16(dst, src) \
    asm volatile("cp.async.cg.shared.global [%0], [%1], 16;" :: "r"(dst), "l"(src) : "memory")
#define CP_COMMIT() asm volatile("cp.async.commit_group;" ::: "memory")

#define LDSM_X4(r0, r1, r2, r3, addr) \
    asm volatile("ldmatrix.sync.aligned.m8n8.x4.shared.b16 {%0,%1,%2,%3}, [%4];" \
        : "=r"(r0), "=r"(r1), "=r"(r2), "=r"(r3) : "r"(addr))

#define MMA_BF16(d, a, b0v, b1v) \
    asm volatile("mma.sync.aligned.m16n8k16.row.col.f32.bf16.bf16.f32 " \
        "{%0,%1,%2,%3}, {%4,%5,%6,%7}, {%8,%9}, {%0,%1,%2,%3};" \
        : "+f"((d)[0]), "+f"((d)[1]), "+f"((d)[2]), "+f"((d)[3]) \
        : "r"((a)[0]), "r"((a)[1]), "r"((a)[2]), "r"((a)[3]), "r"(b0v), "r"(b1v))

__device__ __forceinline__ void split2(float x, __nv_bfloat16& h, __nv_bfloat16& l) {
    h = __float2bfloat16_rn(x);
    l = __float2bfloat16_rn(x - __bfloat162float(h));
}

// MUFU-free exp: rel err ~2e-7, clamped
__device__ __forceinline__ float fexp(float x) {
    float t = x * 1.4426950408889634f;
    t = fminf(fmaxf(t, -126.f), 126.f);
    float fi = rintf(t);
    float f = t - fi;
    float p = 1.5403530393e-4f;
    p = p * f + 1.3333558146e-3f;
    p = p * f + 9.6181291076e-3f;
    p = p * f + 5.5504108664e-2f;
    p = p * f + 2.4022650696e-1f;
    p = p * f + 6.9314718056e-1f;
    p = p * f + 1.0f;
    int ei = (int)fi;
    return __int_as_float((uint32_t)(ei + 127) << 23) * p;
}

// MUFU-free reciprocal (Newton, 3 iters)
__device__ __forceinline__ float frcp(float d) {
    float r = __int_as_float(0x7EF311C3u - __float_as_int(d));
    r = r * (2.f - d * r);
    r = r * (2.f - d * r);
    r = r * (2.f - d * r);
    return r;
}

#define GETC(v, i) ((i) == 0 ? (v).x : (i) == 1 ? (v).y : (i) == 2 ? (v).z : (v).w)

// ---------------- HMMA GEMM, bf16 hi/lo, 128x128, 2 CTAs/SM -------------------
// (unchanged R15/R16 champion)
#define GBM 128
#define GBN 128
#define GK  32
#define TAH (GBM*64)
#define TBH (GBN*64)

template<int MODE, int NTERMS>
__global__ void __launch_bounds__(256, 2)
gemm_mma(const __nv_bfloat16* __restrict__ Ah, const __nv_bfloat16* __restrict__ Al,
         const __nv_bfloat16* __restrict__ Bh, const __nv_bfloat16* __restrict__ Bl,
         float* __restrict__ C,
         __nv_bfloat16* __restrict__ Ho, __nv_bfloat16* __restrict__ Lo,
         int M, int N, int K)
{
    constexpr int STAGE_B = (NTERMS == 3 ? 4 : 3) * TAH;
    constexpr int NSTG    = (NTERMS == 3 ? 3 : 4);
    constexpr int PREF    = NSTG - 1;
    extern __shared__ __align__(128) char smem[];

    const int tid  = threadIdx.x;
    const int lane = tid & 31;
    const int wid  = tid >> 5;
    const int wm   = wid >> 2;
    const int wn   = wid & 3;
    const int bm   = blockIdx.y * GBM;
    const int bn   = blockIdx.x * GBN;

    const int NK = K / GK;
    const uint32_t sbase = smem_u32(smem);

    const int lrow = tid >> 2;
    const int lcc  = tid & 3;

    auto load_stage = [&](int s, int kc) {
        const uint32_t st = sbase + s * STAGE_B;
#pragma unroll
        for (int half = 0; half < 2; half++) {
            const int row = lrow + half * 64;
            const uint32_t swz = (uint32_t)(row * 64 + ((lcc ^ ((row >> 1) & 3)) << 4));
            const size_t ao = (size_t)(bm + row) * K + kc * GK + lcc * 8;
            const size_t bo = (size_t)(bn + row) * K + kc * GK + lcc * 8;
            CP_ASYNC16(st + swz,               Ah + ao);
            CP_ASYNC16(st + TAH + swz,         Al + ao);
            CP_ASYNC16(st + 2*TAH + swz,       Bh + bo);
            if (NTERMS == 3)
                CP_ASYNC16(st + 3*TAH + swz,   Bl + bo);
        }
    };

    float acc[4][4][4];
#pragma unroll
    for (int mi = 0; mi < 4; mi++)
#pragma unroll
        for (int ni = 0; ni < 4; ni++)
#pragma unroll
            for (int r = 0; r < 4; r++) acc[mi][ni][r] = 0.f;

#pragma unroll
    for (int s = 0; s < PREF; s++) { load_stage(s, s); CP_COMMIT(); }

    const int m_idx = lane >> 3;
    int scur = 0, sload = PREF;

    for (int c = 0; c < NK; c++) {
        if (NSTG == 4)
            asm volatile("cp.async.wait_group 2;" ::: "memory");
        else
            asm volatile("cp.async.wait_group 1;" ::: "memory");
        __syncthreads();
        if (c + PREF < NK) load_stage(sload, c + PREF);
        CP_COMMIT();
        if (++sload == NSTG) sload = 0;

        const uint32_t st = sbase + scur * STAGE_B;
        if (++scur == NSTG) scur = 0;

#pragma unroll
        for (int ks = 0; ks < 2; ks++) {
            uint32_t afh[4][4], afl[4][4], bfh[2][4], bfl[2][4];
#pragma unroll
            for (int mi = 0; mi < 4; mi++) {
                const int row = wm * 64 + mi * 16 + (lane & 7) + ((m_idx & 1) << 3);
                const int cch = 2 * ks + (m_idx >> 1);
                const uint32_t off = (uint32_t)(row * 64 + ((cch ^ ((row >> 1) & 3)) << 4));
                LDSM_X4(afh[mi][0], afh[mi][1], afh[mi][2], afh[mi][3], st + off);
                LDSM_X4(afl[mi][0], afl[mi][1], afl[mi][2], afl[mi][3], st + TAH + off);
            }
#pragma unroll
            for (int pi = 0; pi < 2; pi++) {
                const int nrow = wn * 32 + pi * 16 + (lane & 7) + ((m_idx >> 1) << 3);
                const int cch = 2 * ks + (m_idx & 1);
                const uint32_t off = (uint32_t)(nrow * 64 + ((cch ^ ((nrow >> 1) & 3)) << 4));
                LDSM_X4(bfh[pi][0], bfh[pi][1], bfh[pi][2], bfh[pi][3], st + 2*TAH + off);
                if (NTERMS == 3)
                    LDSM_X4(bfl[pi][0], bfl[pi][1], bfl[pi][2], bfl[pi][3], st + 2*TAH + TBH + off);
            }
#pragma unroll
            for (int mi = 0; mi < 4; mi++)
#pragma unroll
                for (int ni = 0; ni < 4; ni++)
                    MMA_BF16(acc[mi][ni], afh[mi],
                             bfh[ni >> 1][(ni & 1) * 2], bfh[ni >> 1][(ni & 1) * 2 + 1]);
#pragma unroll
            for (int mi = 0; mi < 4; mi++)
#pragma unroll
                for (int ni = 0; ni < 4; ni++)
                    MMA_BF16(acc[mi][ni], afl[mi],
                             bfh[ni >> 1][(ni & 1) * 2], bfh[ni >> 1][(ni & 1) * 2 + 1]);
            if (NTERMS == 3) {
#pragma unroll
                for (int mi = 0; mi < 4; mi++)
#pragma unroll
                    for (int ni = 0; ni < 4; ni++)
                        MMA_BF16(acc[mi][ni], afh[mi],
                                 bfl[ni >> 1][(ni & 1) * 2], bfl[ni >> 1][(ni & 1) * 2 + 1]);
            }
        }
    }

#pragma unroll
    for (int mi = 0; mi < 4; mi++) {
        const int row0 = bm + wm * 64 + mi * 16 + (lane >> 2);
#pragma unroll
        for (int ni = 0; ni < 4; ni++) {
            const int col = bn + wn * 32 + ni * 8 + (lane & 3) * 2;
            if (MODE == 0) {
                *(float2*)(C + (size_t)row0 * N + col)       = make_float2(acc[mi][ni][0], acc[mi][ni][1]);
                *(float2*)(C + (size_t)(row0 + 8) * N + col) = make_float2(acc[mi][ni][2], acc[mi][ni][3]);
            } else {
                const int Nout = N >> 1;
                const int j = col >> 1;
                float y0 = acc[mi][ni][0], gt0 = acc[mi][ni][1];
                float y1 = acc[mi][ni][2], gt1 = acc[mi][ni][3];
                float h0 = y0 * gt0 * frcp(1.f + fexp(-gt0));
                float h1 = y1 * gt1 * frcp(1.f + fexp(-gt1));
                __nv_bfloat16 hh, ll;
                split2(h0, hh, ll);
                Ho[(size_t)row0 * Nout + j] = hh;
                Lo[(size_t)row0 * Nout + j] = ll;
                split2(h1, hh, ll);
                Ho[(size_t)(row0 + 8) * Nout + j] = hh;
                Lo[(size_t)(row0 + 8) * Nout + j] = ll;
            }
        }
    }
}

// ---------------- weight splits -----------------------------------------------
#define NW_WQ  (3*D_MODEL*D_MODEL/4)
#define NW_WO  (D_MODEL*D_MODEL/4)
#define NW_A   (NW_WQ + NW_WO)
#define NW_W1  (2*FF*D_MODEL/4)
#define NW_W2  (D_MODEL*FF/4)
#define NW_B   (NW_W1 + NW_W2)

__global__ void __launch_bounds__(256)
split_wA(const float* __restrict__ Wqkv, const float* __restrict__ Wout,
         __nv_bfloat16* __restrict__ wqh, __nv_bfloat16* __restrict__ wql,
         __nv_bfloat16* __restrict__ woh)
{
    int i = blockIdx.x * blockDim.x + threadIdx.x;
    if (i >= NW_A) return;
    if (i < NW_WQ) {
        float4 v = ((const float4*)Wqkv)[i];
        __nv_bfloat16 h[4], l[4];
        split2(v.x, h[0], l[0]); split2(v.y, h[1], l[1]);
        split2(v.z, h[2], l[2]); split2(v.w, h[3], l[3]);
        ((uint2*)wqh)[i] = *(uint2*)h;
        ((uint2*)wql)[i] = *(uint2*)l;
        return;
    }
    size_t o = i - NW_WQ;
    float4 v = ((const float4*)Wout)[o];
    __nv_bfloat16 h[4];
    h[0] = __float2bfloat16_rn(v.x); h[1] = __float2bfloat16_rn(v.y);
    h[2] = __float2bfloat16_rn(v.z); h[3] = __float2bfloat16_rn(v.w);
    ((uint2*)woh)[o] = *(uint2*)h;
}

__global__ void __launch_bounds__(256)
split_wB(const float* __restrict__ W1, const float* __restrict__ W2,
         __nv_bfloat16* __restrict__ w1h, __nv_bfloat16* __restrict__ w2h)
{
    int i = blockIdx.x * blockDim.x + threadIdx.x;
    if (i >= NW_B) return;
    if (i < NW_W1) {
        int flat = i * 4;
        int row = flat >> 10;
        int col = flat & (D_MODEL - 1);
        int prow = (row < FF) ? (2 * row) : (2 * (row - FF) + 1);
        float4 v = ((const float4*)W1)[i];
        __nv_bfloat16 h[4];
        h[0] = __float2bfloat16_rn(v.x); h[1] = __float2bfloat16_rn(v.y);
        h[2] = __float2bfloat16_rn(v.z); h[3] = __float2bfloat16_rn(v.w);
        ((uint2*)w1h)[((size_t)prow * D_MODEL + col) >> 2] = *(uint2*)h;
        return;
    }
    size_t o = i - NW_W1;
    float4 v = ((const float4*)W2)[o];
    __nv_bfloat16 h[4];
    h[0] = __float2bfloat16_rn(v.x); h[1] = __float2bfloat16_rn(v.y);
    h[2] = __float2bfloat16_rn(v.z); h[3] = __float2bfloat16_rn(v.w);
    ((uint2*)w2h)[o] = *(uint2*)h;
}

// ---------------- x split + rope table ----------------------------------------
#define NX_X   (MTOT*D_MODEL/4)
#define NX_ROPE (SEQ*32)
#define NX_TOTAL (NX_X + NX_ROPE)

__global__ void __launch_bounds__(256)
split_x_rope(const float* __restrict__ x,
             __nv_bfloat16* __restrict__ xh, __nv_bfloat16* __restrict__ xl,
             float* __restrict__ rope)
{
    int i = blockIdx.x * blockDim.x + threadIdx.x;
    if (i >= NX_TOTAL) return;
    if (i >= NX_X) {
        int j = i - NX_X;
        int t = j >> 5, dd = j & 31;
        float inv = powf(10000.0f, -(float)dd / 32.0f);
        float s, c;
        sincosf((float)t * inv, &s, &c);
        rope[t * 64 + dd]      = c;
        rope[t * 64 + 32 + dd] = s;
        return;
    }
    float4 v = ((const float4*)x)[i];
    __nv_bfloat16 h[4], l[4];
    split2(v.x, h[0], l[0]); split2(v.y, h[1], l[1]);
    split2(v.z, h[2], l[2]); split2(v.w, h[3], l[3]);
    ((uint2*)xh)[i] = *(uint2*)h;
    ((uint2*)xl)[i] = *(uint2*)l;
}

// ---------------- banded attention v7: HMMA scores + HMMA PV -------------------
// Smem: Kh/Kl bf16 [320][72] (144B pitch; region reused as S fp32 [64][PADS],
//       whose rows also host Ph/Pl bf16), Qh/Ql bf16 [64][72],
//       VTh/VTl bf16 transposed [64 dims][328 keys] (656B pitch).
#define QTILE 64
#define NKMAX 320
#define QKPITCH 72          // bf16 elems per K/Q row (144 B)
#define PADS  332           // S fp32 row stride (1328 B; 332w === 4 mod 8)
#define VTP   328           // VT bf16 row stride (656 B; 164w === 4 mod 8)
#define NCH2  5
#define OFF_KL  46080
#define OFF_QH  92160
#define OFF_QL  101376
#define OFF_VTH 110592
#define OFF_VTL 152576
#define ATTN_SMEM 194560

__global__ void __launch_bounds__(512)
attn_kernel(const float* __restrict__ qkv, const float* __restrict__ rope,
            __nv_bfloat16* __restrict__ OH, __nv_bfloat16* __restrict__ OL)
{
    extern __shared__ __align__(128) char smc[];
    __nv_bfloat16* KhP = (__nv_bfloat16*)(smc);
    __nv_bfloat16* KlP = (__nv_bfloat16*)(smc + OFF_KL);
    __nv_bfloat16* QhP = (__nv_bfloat16*)(smc + OFF_QH);
    __nv_bfloat16* QlP = (__nv_bfloat16*)(smc + OFF_QL);
    __nv_bfloat16* VTh = (__nv_bfloat16*)(smc + OFF_VTH);
    __nv_bfloat16* VTl = (__nv_bfloat16*)(smc + OFF_VTL);
    float* S  = (float*)smc;                       // aliases K region after scores
    const uint32_t sb = smem_u32(smc);

    const int bh = blockIdx.y;
    const int b = bh >> 4, h = bh & 15;
    const int q0 = blockIdx.x * QTILE;
    const int klo = max(0, q0 - 127);
    const int khi = min(SEQ - 1, q0 + QTILE - 1 + 128);
    const int nk = khi - klo + 1;

    const int tid = threadIdx.x;

    // ---- load K (rope'd bf16 h/l) + V transposed (bf16 h/l) ----
    for (int i = tid; i < nk * 32; i += 512) {
        int r = i >> 5, dd = i & 31;
        int t = klo + r;
        const float* base = qkv + (size_t)(b * SEQ + t) * (3 * D_MODEL) + h * HEAD_DIM;
        float c0 = rope[t * 64 + dd], s0 = rope[t * 64 + 32 + dd];
        float k1 = base[D_MODEL + dd], k2 = base[D_MODEL + 32 + dd];
        __nv_bfloat16 hh, ll;
        split2(k1 * c0 - k2 * s0, hh, ll);
        KhP[r * QKPITCH + dd] = hh;      KlP[r * QKPITCH + dd] = ll;
        split2(k2 * c0 + k1 * s0, hh, ll);
        KhP[r * QKPITCH + 32 + dd] = hh; KlP[r * QKPITCH + 32 + dd] = ll;
        split2(base[2 * D_MODEL + dd], hh, ll);
        VTh[dd * VTP + r] = hh;          VTl[dd * VTP + r] = ll;
        split2(base[2 * D_MODEL + 32 + dd], hh, ll);
        VTh[(dd + 32) * VTP + r] = hh;   VTl[(dd + 32) * VTP + r] = ll;
    }
    // zero K rows and VT columns beyond nk
    for (int i = tid; i < (NKMAX - nk) * 64; i += 512) {
        int r = nk + (i >> 6), d = i & 63;
        __nv_bfloat16 z = __float2bfloat16_rn(0.f);
        KhP[r * QKPITCH + d] = z;
        KlP[r * QKPITCH + d] = z;
        VTh[d * VTP + r] = z;
        VTl[d * VTP + r] = z;
    }
    // ---- load Q (rope'd bf16 h/l) ----
    for (int i = tid; i < QTILE * 32; i += 512) {
        int r = i >> 5, dd = i & 31;
        int t = q0 + r;
        const float* base = qkv + (size_t)(b * SEQ + t) * (3 * D_MODEL) + h * HEAD_DIM;
        float c0 = rope[t * 64 + dd], s0 = rope[t * 64 + 32 + dd];
        float q1 = base[dd], q2 = base[32 + dd];
        __nv_bfloat16 hh, ll;
        split2(q1 * c0 - q2 * s0, hh, ll);
        QhP[r * QKPITCH + dd] = hh;      QlP[r * QKPITCH + dd] = ll;
        split2(q2 * c0 + q1 * s0, hh, ll);
        QhP[r * QKPITCH + 32 + dd] = hh; QlP[r * QKPITCH + 32 + dd] = ll;
    }
    __syncthreads();

    const int w = tid >> 5, lane = tid & 31;
    const int m_idx = lane >> 3;

    // ---- score pass via HMMA: warp w -> S[qtileS..+16][keybase..+80] ----
    {
        const int qtileS = (w >> 2) * 16;
        const int keybase = (w & 3) * 80;
        float sacc[10][4];
#pragma unroll
        for (int ni = 0; ni < 10; ni++)
#pragma unroll
            for (int r = 0; r < 4; r++) sacc[ni][r] = 0.f;

        const int arow = qtileS + (lane & 7) + ((m_idx & 1) << 3);
        const int brow = keybase + (lane & 7) + ((m_idx >> 1) << 3);
#pragma unroll
        for (int dc = 0; dc < 4; dc++) {
            const uint32_t aoff = (uint32_t)(arow * 144 + (2 * dc + (m_idx >> 1)) * 16);
            uint32_t ah[4], al[4];
            LDSM_X4(ah[0], ah[1], ah[2], ah[3], sb + OFF_QH + aoff);
            LDSM_X4(al[0], al[1], al[2], al[3], sb + OFF_QL + aoff);
            const uint32_t bk = (uint32_t)((2 * dc + (m_idx & 1)) * 16);
#pragma unroll
            for (int pp = 0; pp < 5; pp++) {
                const uint32_t boff = (uint32_t)((brow + pp * 16) * 144) + bk;
                uint32_t bhr[4], blr[4];
                LDSM_X4(bhr[0], bhr[1], bhr[2], bhr[3], sb + boff);
                LDSM_X4(blr[0], blr[1], blr[2], blr[3], sb + OFF_KL + boff);
                MMA_BF16(sacc[2*pp],     ah, bhr[0], bhr[1]);
                MMA_BF16(sacc[2*pp + 1], ah, bhr[2], bhr[3]);
                MMA_BF16(sacc[2*pp],     al, bhr[0], bhr[1]);
                MMA_BF16(sacc[2*pp + 1], al, bhr[2], bhr[3]);
                MMA_BF16(sacc[2*pp],     ah, blr[0], blr[1]);
                MMA_BF16(sacc[2*pp + 1], ah, blr[2], blr[3]);
            }
        }
        __syncthreads();        // all K/Q ldmatrix reads complete before S overwrite
        const int srow = qtileS + (lane >> 2);
#pragma unroll
        for (int ni = 0; ni < 10; ni++) {
            const int key = keybase + ni * 8 + (lane & 3) * 2;
            *(float2*)&S[srow * PADS + key]       = make_float2(sacc[ni][0], sacc[ni][1]);
            *(float2*)&S[(srow + 8) * PADS + key] = make_float2(sacc[ni][2], sacc[ni][3]);
        }
    }
    __syncthreads();

    // ---- softmax: warp w owns rows qloc..qloc+3 (read S, write Ph/Pl in-row) -
    const int qloc = w * 4;
    const int qg0 = q0 + qloc;

    float2 acc[4][NCH2];
#pragma unroll
    for (int j = 0; j < 4; j++)
#pragma unroll
        for (int c = 0; c < NCH2; c++)
            acc[j][c] = *(const float2*)&S[(qloc + j) * PADS + c * 64 + 2 * lane];

    float inv[4];
#pragma unroll
    for (int j = 0; j < 4; j++) {
        const int qg = qg0 + j;
        const int lo = max(0, qg - 127) - klo;
        const int hi = min(SEQ - 1, qg + 128) - klo;
        float m = -1e30f;
#pragma unroll
        for (int c = 0; c < NCH2; c++) {
            int kg = c * 64 + 2 * lane;
            float sx = (kg     >= lo && kg     <= hi) ? acc[j][c].x * 0.125f : -1e30f;
            float sy = (kg + 1 >= lo && kg + 1 <= hi) ? acc[j][c].y * 0.125f : -1e30f;
            acc[j][c].x = sx; acc[j][c].y = sy;
            m = fmaxf(m, fmaxf(sx, sy));
        }
#pragma unroll
        for (int o = 16; o; o >>= 1) m = fmaxf(m, __shfl_xor_sync(0xffffffffu, m, o));
        float sum = 0.f;
#pragma unroll
        for (int c = 0; c < NCH2; c++) {
            float ex = fexp(acc[j][c].x - m);
            float ey = fexp(acc[j][c].y - m);
            acc[j][c].x = ex; acc[j][c].y = ey;
            sum += ex + ey;
        }
#pragma unroll
        for (int o = 16; o; o >>= 1) sum += __shfl_xor_sync(0xffffffffu, sum, o);
        inv[j] = frcp(sum);
    }

    // write normalized P as bf16 h/l into the S rows (row-exclusive per warp)
    // Ph at row*1328 + key*2 ; Pl at row*1328 + 672 + key*2
#pragma unroll
    for (int j = 0; j < 4; j++) {
        char* prow = smc + (qloc + j) * (PADS * 4);
#pragma unroll
        for (int c = 0; c < NCH2; c++) {
            float px = acc[j][c].x * inv[j];
            float py = acc[j][c].y * inv[j];
            __nv_bfloat16 hx, lx, hy, ly;
            split2(px, hx, lx);
            split2(py, hy, ly);
            __nv_bfloat162 hp; hp.x = hx; hp.y = hy;
            __nv_bfloat162 lp; lp.x = lx; lp.y = ly;
            int key = c * 64 + 2 * lane;
            *(__nv_bfloat162*)(prow + key * 2)       = hp;
            *(__nv_bfloat162*)(prow + 672 + key * 2) = lp;
        }
    }
    __syncthreads();

    // ---- PV via HMMA: warp w -> O[qtileP..+16][dbase..+16], K = 320 keys ----
    {
        const int qtileP = (w >> 2) * 16;
        const int dbase  = (w & 3) * 16;
        float oacc[2][4];
#pragma unroll
        for (int nh = 0; nh < 2; nh++)
#pragma unroll
            for (int r = 0; r < 4; r++) oacc[nh][r] = 0.f;

        const int arow = qtileP + (lane & 7) + ((m_idx & 1) << 3);
        const int brow = dbase + (lane & 7) + ((m_idx >> 1) << 3);
        const uint32_t abase = sb + (uint32_t)(arow * (PADS * 4)) + (m_idx >> 1) * 16;
        const uint32_t bbase = (uint32_t)(brow * (VTP * 2)) + (m_idx & 1) * 16;
#pragma unroll
        for (int kc = 0; kc < 20; kc++) {
            uint32_t ah[4], al[4], bhr[4], blr[4];
            LDSM_X4(ah[0], ah[1], ah[2], ah[3], abase + kc * 32);
            LDSM_X4(al[0], al[1], al[2], al[3], abase + 672 + kc * 32);
            LDSM_X4(bhr[0], bhr[1], bhr[2], bhr[3], sb + OFF_VTH + bbase + kc * 32);
            LDSM_X4(blr[0], blr[1], blr[2], blr[3], sb + OFF_VTL + bbase + kc * 32);
            MMA_BF16(oacc[0], ah, bhr[0], bhr[1]);
            MMA_BF16(oacc[1], ah, bhr[2], bhr[3]);
            MMA_BF16(oacc[0], al, bhr[0], bhr[1]);
            MMA_BF16(oacc[1], al, bhr[2], bhr[3]);
            MMA_BF16(oacc[0], ah, blr[0], blr[1]);
            MMA_BF16(oacc[1], ah, blr[2], blr[3]);
        }

        // ---- write O as bf16 h/l ----
        const int row0 = qtileP + (lane >> 2);
#pragma unroll
        for (int nh = 0; nh < 2; nh++) {
            const int d = dbase + nh * 8 + (lane & 3) * 2;
#pragma unroll
            for (int half = 0; half < 2; half++) {
                const int qg = q0 + row0 + half * 8;
                size_t ob = ((size_t)(b * SEQ + qg)) * D_MODEL + h * HEAD_DIM + d;
                __nv_bfloat16 hx, lx, hy, ly;
                split2(oacc[nh][half * 2 + 0], hx, lx);
                split2(oacc[nh][half * 2 + 1], hy, ly);
                __nv_bfloat162 hp; hp.x = hx; hp.y = hy;
                __nv_bfloat162 lp; lp.x = lx; lp.y = ly;
                *(__nv_bfloat162*)(OH + ob) = hp;
                *(__nv_bfloat162*)(OL + ob) = lp;
            }
        }
    }
}

// ---------------- residual + (opt bias) + RMSNorm (+opt bf16 split out) ------
__global__ void __launch_bounds__(256)
resid_rmsnorm(const float* __restrict__ A, const float* __restrict__ bias,
              const float* __restrict__ R, const float* __restrict__ g,
              float* __restrict__ out,
              __nv_bfloat16* __restrict__ outH, __nv_bfloat16* __restrict__ outL)
{
    const int row = blockIdx.x;
    const float* a = A + (size_t)row * D_MODEL;
    const float* r = R + (size_t)row * D_MODEL;

    float v[4];
    float ss = 0.f;
#pragma unroll
    for (int i = 0; i < 4; i++) {
        int c = threadIdx.x + i * 256;
        float x = a[c] + ALPHA * r[c];
        if (bias) x += bias[c];
        v[i] = x;
        ss += x * x;
    }
#pragma unroll
    for (int o = 16; o; o >>= 1) ss += __shfl_xor_sync(0xffffffffu, ss, o);

    __shared__ float ws[8];
    if ((threadIdx.x & 31) == 0) ws[threadIdx.x >> 5] = ss;
    __syncthreads();
    if (threadIdx.x < 32) {
        float t = (threadIdx.x < 8) ? ws[threadIdx.x] : 0.f;
#pragma unroll
        for (int o = 4; o; o >>= 1) t += __shfl_xor_sync(0xffffffffu, t, o);
        if (threadIdx.x == 0) ws[0] = t;
    }
    __syncthreads();
    const float rms = rsqrtf(ws[0] * (1.0f / D_MODEL) + EPS);

    float* orow = out + (size_t)row * D_MODEL;
#pragma unroll
    for (int i = 0; i < 4; i++) {
        int c = threadIdx.x + i * 256;
        float y = v[i] * rms * g[c];
        orow[c] = y;
        if (outH) {
            __nv_bfloat16 h, l;
            split2(y, h, l);
            outH[(size_t)row * D_MODEL + c] = h;
            outL[(size_t)row * D_MODEL + c] = l;
        }
    }
}

// ---------------- host orchestration -----------------------------------------
template<int MODE, int NTERMS>
static void launch_gemm(const __nv_bfloat16* Ah, const __nv_bfloat16* Al,
                        const __nv_bfloat16* Bh, const __nv_bfloat16* Bl,
                        float* C, __nv_bfloat16* Ho, __nv_bfloat16* Lo,
                        int M, int N, int K)
{
    const int stage = (NTERMS == 3 ? 4 : 3) * TAH;
    const int nstg  = (NTERMS == 3 ? 3 : 4);
    size_t smem = (size_t)nstg * stage;
    cudaFuncSetAttribute(gemm_mma<MODE, NTERMS>, cudaFuncAttributeMaxDynamicSharedMemorySize, (int)smem);
    dim3 grid(N / GBN, M / GBM);
    gemm_mma<MODE, NTERMS><<<grid, 256, smem>>>(Ah, Al, Bh, Bl, C, Ho, Lo, M, N, K);
}

extern "C" void kernel_launch(void* const* d_in, const int* in_sizes, int n_in,
                              void* d_out, int out_size)
{
    const float* x    = (const float*)d_in[0];
    const float* Wqkv = (const float*)d_in[1];
    const float* Wout = (const float*)d_in[2];
    const float* bout = (const float*)d_in[3];
    const float* W1   = (const float*)d_in[4];
    const float* W2   = (const float*)d_in[5];
    const float* g1   = (const float*)d_in[6];
    const float* g2   = (const float*)d_in[7];
    float* out = (float*)d_out;

    float *qkv, *Ap, *x2, *y2, *rope;
    cudaGetSymbolAddress((void**)&qkv,  g_qkv);
    cudaGetSymbolAddress((void**)&Ap,   g_a);
    cudaGetSymbolAddress((void**)&x2,   g_x2);
    cudaGetSymbolAddress((void**)&y2,   g_y2);
    cudaGetSymbolAddress((void**)&rope, g_rope);

    __nv_bfloat16 *xh,*xl,*oh,*ol,*x2h,*x2l,*hbh,*hbl,*wqh,*wql,*woh,*w1h,*w2h;
    cudaGetSymbolAddress((void**)&xh,  g_xh);  cudaGetSymbolAddress((void**)&xl,  g_xl);
    cudaGetSymbolAddress((void**)&oh,  g_oh);  cudaGetSymbolAddress((void**)&ol,  g_ol);
    cudaGetSymbolAddress((void**)&x2h, g_x2h); cudaGetSymbolAddress((void**)&x2l, g_x2l);
    cudaGetSymbolAddress((void**)&hbh, g_hbh); cudaGetSymbolAddress((void**)&hbl, g_hbl);
    cudaGetSymbolAddress((void**)&wqh, g_wqh); cudaGetSymbolAddress((void**)&wql, g_wql);
    cudaGetSymbolAddress((void**)&woh, g_woh);
    cudaGetSymbolAddress((void**)&w1h, g_w1h);
    cudaGetSymbolAddress((void**)&w2h, g_w2h);

    // 0) weight split A (Wqkv hi+lo, Wout hi)                          [launch 0]
    split_wA<<<(NW_A + 255) / 256, 256>>>(Wqkv, Wout, wqh, wql, woh);

    // 1) weight split B (W1 perm hi, W2 hi)                            [launch 1]
    split_wB<<<(NW_B + 255) / 256, 256>>>(W1, W2, w1h, w2h);

    // 2) x split + rope table                                          [launch 2]
    split_x_rope<<<(NX_TOTAL + 255) / 256, 256>>>(x, xh, xl, rope);

    // 3) QKV = X @ Wqkv^T  (3-term)                       [launch 3 -> profiled]
    launch_gemm<0, 3>(xh, xl, wqh, wql, qkv, nullptr, nullptr, MTOT, 3 * D_MODEL, D_MODEL);

    // 4) banded attention (rope fused, HMMA scores + PV) -> oh/ol      [launch 4]
    {
        cudaFuncSetAttribute(attn_kernel, cudaFuncAttributeMaxDynamicSharedMemorySize, (int)ATTN_SMEM);
        dim3 grid(SEQ / QTILE, BATCH * NHEAD);
        attn_kernel<<<grid, 512, ATTN_SMEM>>>(qkv, rope, oh, ol);
    }

    // 5) A = O @ Wout^T  (2-term, 4-stage)                             [launch 5]
    launch_gemm<0, 2>(oh, ol, woh, nullptr, Ap, nullptr, nullptr, MTOT, D_MODEL, D_MODEL);

    // 6) x2 = rmsnorm(A + bout + ALPHA*x, g1) (+ bf16 split)           [launch 6]
    resid_rmsnorm<<<MTOT, 256>>>(Ap, bout, x, g1, x2, x2h, x2l);

    // 7) fused: [y|gate] = x2 @ W1perm^T, swiglu (2-term, 4-stage)     [launch 7]
    launch_gemm<1, 2>(x2h, x2l, w1h, nullptr, nullptr, hbh, hbl, MTOT, 2 * FF, D_MODEL);

    // 8) Y2 = H @ W2^T  (K = FF, 2-term, 4-stage)                      [launch 8]
    launch_gemm<0, 2>(hbh, hbl, w2h, nullptr, y2, nullptr, nullptr, MTOT, D_MODEL, FF);

    // 9) out = rmsnorm(Y2 + ALPHA*x2, g2)                              [launch 9]
    resid_rmsnorm<<<MTOT, 256>>>(y2, nullptr, x2, g2, out, nullptr, nullptr);
}